// round 1
// baseline (speedup 1.0000x reference)
#include <cuda_runtime.h>
#include <math.h>

// Problem constants
#define Bsz 4
#define Sq  2048
#define Dm  1024
#define Hh  16
#define HD  64
#define MTOT (Bsz * Sq)   // 8192

// Scratch (device globals — no allocation allowed)
__device__ float g_xq[(size_t)MTOT * Dm];
__device__ float g_xk[(size_t)MTOT * Dm];
__device__ float g_xv[(size_t)MTOT * Dm];
__device__ float g_ao[(size_t)MTOT * Dm];

// ---------------------------------------------------------------------------
// GEMM: C[m,n] = sum_k A[m,k] * W[n,k]   (y = x @ W^T, both K-major)
// BM=BN=128, BK=16, 256 threads, 8x8 register tile per thread.
// asel: 0 -> A=Ap, 1 -> A=g_ao
// csel: 0 -> C=Cp, 1 -> g_xq, 2 -> g_xk, 3 -> g_xv
// ---------------------------------------------------------------------------
__global__ __launch_bounds__(256) void gemm_xwT(const float* __restrict__ Ap,
                                                const float* __restrict__ W,
                                                float* __restrict__ Cp,
                                                int asel, int csel,
                                                int M, int N, int K)
{
    const float* A = asel ? g_ao : Ap;
    float* C = (csel == 0) ? Cp : (csel == 1 ? g_xq : (csel == 2 ? g_xk : g_xv));

    __shared__ float As[16][128];
    __shared__ float Bs[16][128];

    const int tid = threadIdx.x;
    const int tx = tid & 15;
    const int ty = tid >> 4;
    const int row0 = blockIdx.y * 128;
    const int col0 = blockIdx.x * 128;

    float acc[8][8];
    #pragma unroll
    for (int i = 0; i < 8; i++)
        #pragma unroll
        for (int j = 0; j < 8; j++) acc[i][j] = 0.f;

    for (int kb = 0; kb < K; kb += 16) {
        #pragma unroll
        for (int p = 0; p < 2; p++) {
            int idx = tid + p * 256;       // 0..511
            int r   = idx >> 2;            // 0..127
            int cq  = idx & 3;             // 0..3 (float4 within 16-wide k slab)
            float4 va = *reinterpret_cast<const float4*>(
                &A[(size_t)(row0 + r) * K + kb + cq * 4]);
            As[cq * 4 + 0][r] = va.x;
            As[cq * 4 + 1][r] = va.y;
            As[cq * 4 + 2][r] = va.z;
            As[cq * 4 + 3][r] = va.w;
            float4 vb = *reinterpret_cast<const float4*>(
                &W[(size_t)(col0 + r) * K + kb + cq * 4]);
            Bs[cq * 4 + 0][r] = vb.x;
            Bs[cq * 4 + 1][r] = vb.y;
            Bs[cq * 4 + 2][r] = vb.z;
            Bs[cq * 4 + 3][r] = vb.w;
        }
        __syncthreads();

        #pragma unroll
        for (int k = 0; k < 16; k++) {
            float a[8], b[8];
            #pragma unroll
            for (int i = 0; i < 8; i++) a[i] = As[k][ty + 16 * i];
            #pragma unroll
            for (int j = 0; j < 8; j++) b[j] = Bs[k][tx + 16 * j];
            #pragma unroll
            for (int i = 0; i < 8; i++)
                #pragma unroll
                for (int j = 0; j < 8; j++)
                    acc[i][j] = fmaf(a[i], b[j], acc[i][j]);
        }
        __syncthreads();
    }

    #pragma unroll
    for (int i = 0; i < 8; i++) {
        int m = row0 + ty + 16 * i;
        #pragma unroll
        for (int j = 0; j < 8; j++) {
            C[(size_t)m * N + col0 + tx + 16 * j] = acc[i][j];
        }
    }
}

// ---------------------------------------------------------------------------
// Flash attention (causal), fp32. One block = one (b,h) x 64-row Q tile.
// BQ=64, BKV=32, HD=64. 256 threads (16x16), online softmax.
// ---------------------------------------------------------------------------
#define BQ  64
#define BKV 32

__global__ __launch_bounds__(256) void flash_attn()
{
    const int qt = blockIdx.x;       // 0..31
    const int bh = blockIdx.y;       // 0..63
    const int b  = bh / Hh;
    const int h  = bh % Hh;
    const int q0 = qt * BQ;

    const size_t base = (size_t)b * Sq * Dm + (size_t)h * HD;
    const float* Qp = g_xq + base;
    const float* Kp = g_xk + base;
    const float* Vp = g_xv + base;
    float*       Op = g_ao + base;

    __shared__ float Qs[BQ][HD + 1];
    __shared__ float Ks[BKV][HD + 1];
    __shared__ float Vs[BKV][HD + 1];
    __shared__ float Ss[BQ][BKV + 1];
    __shared__ float row_m[BQ], row_l[BQ], row_sc[BQ];

    const int tid = threadIdx.x;
    const int tx = tid & 15;
    const int ty = tid >> 4;

    // Load 64x64 Q tile (1024 float4, 4 per thread)
    #pragma unroll
    for (int p = 0; p < 4; p++) {
        int idx = tid + p * 256;      // 0..1023
        int r   = idx >> 4;           // 0..63
        int c4  = idx & 15;           // 0..15
        float4 v = *reinterpret_cast<const float4*>(
            &Qp[(size_t)(q0 + r) * Dm + c4 * 4]);
        Qs[r][c4 * 4 + 0] = v.x;
        Qs[r][c4 * 4 + 1] = v.y;
        Qs[r][c4 * 4 + 2] = v.z;
        Qs[r][c4 * 4 + 3] = v.w;
    }
    if (tid < BQ) { row_m[tid] = -INFINITY; row_l[tid] = 0.f; }

    float o[4][4];
    #pragma unroll
    for (int i = 0; i < 4; i++)
        #pragma unroll
        for (int j = 0; j < 4; j++) o[i][j] = 0.f;

    const int ntiles = 2 * qt + 2;   // causal: kv cols up to q0+63
    for (int jt = 0; jt < ntiles; jt++) {
        __syncthreads();  // protects Q first iter; K/V/Ss reuse afterwards

        // Load 32x64 K and V tiles (512 float4 each, 2 per thread each)
        #pragma unroll
        for (int p = 0; p < 2; p++) {
            int idx = tid + p * 256;   // 0..511
            int r   = idx >> 4;        // 0..31
            int c4  = idx & 15;
            size_t off = (size_t)(jt * BKV + r) * Dm + c4 * 4;
            float4 vk = *reinterpret_cast<const float4*>(&Kp[off]);
            Ks[r][c4 * 4 + 0] = vk.x; Ks[r][c4 * 4 + 1] = vk.y;
            Ks[r][c4 * 4 + 2] = vk.z; Ks[r][c4 * 4 + 3] = vk.w;
            float4 vv = *reinterpret_cast<const float4*>(&Vp[off]);
            Vs[r][c4 * 4 + 0] = vv.x; Vs[r][c4 * 4 + 1] = vv.y;
            Vs[r][c4 * 4 + 2] = vv.z; Vs[r][c4 * 4 + 3] = vv.w;
        }
        __syncthreads();

        // S = Q K^T * (1/sqrt(HD)); each thread 4x2 of the 64x32 tile
        float s[4][2];
        #pragma unroll
        for (int i = 0; i < 4; i++) { s[i][0] = 0.f; s[i][1] = 0.f; }
        #pragma unroll
        for (int d = 0; d < HD; d++) {
            float a0 = Qs[ty][d], a1 = Qs[ty + 16][d];
            float a2 = Qs[ty + 32][d], a3 = Qs[ty + 48][d];
            float b0 = Ks[tx][d], b1 = Ks[tx + 16][d];
            s[0][0] = fmaf(a0, b0, s[0][0]); s[0][1] = fmaf(a0, b1, s[0][1]);
            s[1][0] = fmaf(a1, b0, s[1][0]); s[1][1] = fmaf(a1, b1, s[1][1]);
            s[2][0] = fmaf(a2, b0, s[2][0]); s[2][1] = fmaf(a2, b1, s[2][1]);
            s[3][0] = fmaf(a3, b0, s[3][0]); s[3][1] = fmaf(a3, b1, s[3][1]);
        }
        const float smul = 0.125f;  // 1/sqrt(64)
        #pragma unroll
        for (int i = 0; i < 4; i++) {
            int r = ty + 16 * i;
            #pragma unroll
            for (int jj = 0; jj < 2; jj++) {
                int c = tx + 16 * jj;
                float val = s[i][jj] * smul;
                if (jt * BKV + c > q0 + r) val = -INFINITY;  // causal mask
                Ss[r][c] = val;
            }
        }
        __syncthreads();

        // Online softmax update: one thread per row
        if (tid < BQ) {
            int r = tid;
            float m_old = row_m[r];
            float m = m_old;
            #pragma unroll
            for (int c = 0; c < BKV; c++) m = fmaxf(m, Ss[r][c]);
            float sc = __expf(m_old - m);   // 0 on first live tile
            float l = row_l[r] * sc;
            #pragma unroll
            for (int c = 0; c < BKV; c++) {
                float pv = __expf(Ss[r][c] - m);
                Ss[r][c] = pv;
                l += pv;
            }
            row_m[r] = m; row_l[r] = l; row_sc[r] = sc;
        }
        __syncthreads();

        // O = O * row_sc + P @ V ; each thread 4x4 patch (rows ty+16i, cols tx+16j)
        #pragma unroll
        for (int i = 0; i < 4; i++) {
            float sc = row_sc[ty + 16 * i];
            #pragma unroll
            for (int j = 0; j < 4; j++) o[i][j] *= sc;
        }
        #pragma unroll
        for (int k = 0; k < BKV; k++) {
            float p0 = Ss[ty][k], p1 = Ss[ty + 16][k];
            float p2 = Ss[ty + 32][k], p3 = Ss[ty + 48][k];
            float v0 = Vs[k][tx], v1 = Vs[k][tx + 16];
            float v2 = Vs[k][tx + 32], v3 = Vs[k][tx + 48];
            o[0][0] = fmaf(p0, v0, o[0][0]); o[0][1] = fmaf(p0, v1, o[0][1]);
            o[0][2] = fmaf(p0, v2, o[0][2]); o[0][3] = fmaf(p0, v3, o[0][3]);
            o[1][0] = fmaf(p1, v0, o[1][0]); o[1][1] = fmaf(p1, v1, o[1][1]);
            o[1][2] = fmaf(p1, v2, o[1][2]); o[1][3] = fmaf(p1, v3, o[1][3]);
            o[2][0] = fmaf(p2, v0, o[2][0]); o[2][1] = fmaf(p2, v1, o[2][1]);
            o[2][2] = fmaf(p2, v2, o[2][2]); o[2][3] = fmaf(p2, v3, o[2][3]);
            o[3][0] = fmaf(p3, v0, o[3][0]); o[3][1] = fmaf(p3, v1, o[3][1]);
            o[3][2] = fmaf(p3, v2, o[3][2]); o[3][3] = fmaf(p3, v3, o[3][3]);
        }
    }

    // Final normalize + write to [B,S,D] layout with head offset
    #pragma unroll
    for (int i = 0; i < 4; i++) {
        int r = ty + 16 * i;
        float inv_l = 1.f / row_l[r];
        #pragma unroll
        for (int j = 0; j < 4; j++) {
            Op[(size_t)(q0 + r) * Dm + tx + 16 * j] = o[i][j] * inv_l;
        }
    }
}

// ---------------------------------------------------------------------------
// Launch: 3 input projections -> flash attention -> output projection
// ---------------------------------------------------------------------------
extern "C" void kernel_launch(void* const* d_in, const int* in_sizes, int n_in,
                              void* d_out, int out_size)
{
    const float* q  = (const float*)d_in[0];
    const float* k  = (const float*)d_in[1];
    const float* v  = (const float*)d_in[2];
    const float* wq = (const float*)d_in[3];
    const float* wk = (const float*)d_in[4];
    const float* wv = (const float*)d_in[5];
    const float* wo = (const float*)d_in[6];
    float* out = (float*)d_out;

    dim3 ggrid(Dm / 128, MTOT / 128, 1);  // (8, 64)
    gemm_xwT<<<ggrid, 256>>>(q, wq, nullptr, 0, 1, MTOT, Dm, Dm);
    gemm_xwT<<<ggrid, 256>>>(k, wk, nullptr, 0, 2, MTOT, Dm, Dm);
    gemm_xwT<<<ggrid, 256>>>(v, wv, nullptr, 0, 3, MTOT, Dm, Dm);

    dim3 agrid(Sq / BQ, Bsz * Hh, 1);     // (32, 64)
    flash_attn<<<agrid, 256>>>();

    gemm_xwT<<<ggrid, 256>>>(nullptr, wo, out, 1, 0, MTOT, Dm, Dm);
}

// round 4
// speedup vs baseline: 1.7536x; 1.7536x over previous
#include <cuda_runtime.h>
#include <cstdint>
#include <math.h>

// Problem constants
#define Bsz 4
#define Sq  2048
#define Dm  1024
#define Hh  16
#define HD  64
#define MTOT (Bsz * Sq)   // 8192

// Scratch (device globals — no allocation allowed)
__device__ float g_xq[(size_t)MTOT * Dm];
__device__ float g_xk[(size_t)MTOT * Dm];
__device__ float g_xv[(size_t)MTOT * Dm];
__device__ float g_ao[(size_t)MTOT * Dm];

// ===========================================================================
// Helpers: cp.async + tf32 mma.sync (sm_80+ PTX — valid on plain sm_103)
// ===========================================================================
__device__ __forceinline__ uint32_t smem_u32(const void* p) {
    uint32_t a;
    asm("{ .reg .u64 t; cvta.to.shared.u64 t, %1; cvt.u32.u64 %0, t; }"
        : "=r"(a) : "l"(p));
    return a;
}

__device__ __forceinline__ void cp16(uint32_t dst, const void* src) {
    asm volatile("cp.async.cg.shared.global [%0], [%1], 16;"
                 :: "r"(dst), "l"(src));
}
__device__ __forceinline__ void cp_commit() {
    asm volatile("cp.async.commit_group;" ::: "memory");
}
template<int N> __device__ __forceinline__ void cp_wait() {
    asm volatile("cp.async.wait_group %0;" :: "n"(N) : "memory");
}

__device__ __forceinline__ uint32_t f2tf32(float v) {
    uint32_t r;
    asm("cvt.rna.tf32.f32 %0, %1;" : "=r"(r) : "f"(v));
    return r;
}

// D(16x8) += A(16x8) * B(8x8), tf32 inputs, fp32 accumulate
__device__ __forceinline__ void mma_tf32(float* d, const uint32_t* a,
                                         const uint32_t* b) {
    asm volatile(
        "mma.sync.aligned.m16n8k8.row.col.f32.tf32.tf32.f32 "
        "{%0,%1,%2,%3}, {%4,%5,%6,%7}, {%8,%9}, {%0,%1,%2,%3};"
        : "+f"(d[0]), "+f"(d[1]), "+f"(d[2]), "+f"(d[3])
        : "r"(a[0]), "r"(a[1]), "r"(a[2]), "r"(a[3]),
          "r"(b[0]), "r"(b[1]));
}

// ===========================================================================
// Tensor-core GEMM: C[m,n] = sum_k A[m,k] * W[n,k]  (M=8192, N=K=1024)
// 128x128 CTA tile, BK=32, 2-stage cp.async double buffer.
// 8 warps in a 2x4 grid; each warp owns a 64x32 tile = 4x4 m16n8k8 MMAs.
// ===========================================================================
#define BK 32
#define NC (Dm / BK)              // 32 chunks
#define LDA 36                    // 32 + 4 pad floats (16B, keeps cp16 aligned)
#define HALF_OFF (128 * LDA * 4)  // byte offset of W tile within a stage
#define STAGE_BYTES (2 * 128 * LDA * 4)   // 36864
#define GSMEM (2 * STAGE_BYTES)           // 73728

__device__ __forceinline__ void load_chunk(uint32_t sbase, int stage,
                                           const float* A, const float* W,
                                           int row0, int col0, int kb, int tid) {
    uint32_t a_st = sbase + stage * STAGE_BYTES;
    uint32_t w_st = a_st + HALF_OFF;
    #pragma unroll
    for (int p = 0; p < 4; p++) {
        int idx = tid + p * 256;          // 0..1023
        int r  = idx >> 3;                // 0..127
        int cq = idx & 7;                 // 16B unit within 128B of data
        uint32_t d = (uint32_t)(r * (LDA * 4) + cq * 16);
        cp16(a_st + d, A + (size_t)(row0 + r) * Dm + kb + cq * 4);
        cp16(w_st + d, W + (size_t)(col0 + r) * Dm + kb + cq * 4);
    }
    cp_commit();
}

__global__ __launch_bounds__(256) void gemm_tc(const float* __restrict__ Ap,
                                               const float* __restrict__ W,
                                               float* __restrict__ Cp,
                                               int asel, int csel)
{
    extern __shared__ char smem[];
    uint32_t sbase = smem_u32(smem);
    const float* A = asel ? g_ao : Ap;
    float* C = (csel == 0) ? Cp : (csel == 1 ? g_xq : (csel == 2 ? g_xk : g_xv));

    const int tid = threadIdx.x;
    const int wid = tid >> 5;
    const int lid = tid & 31;
    const int g   = lid >> 2;       // groupID 0..7
    const int tg  = lid & 3;        // thread-in-group 0..3
    const int wr  = wid >> 2;       // warp row 0..1  (64 rows each)
    const int wc  = wid & 3;        // warp col 0..3  (32 cols each)
    const int row0 = blockIdx.y * 128;
    const int col0 = blockIdx.x * 128;

    float acc[4][4][4];
    #pragma unroll
    for (int mt = 0; mt < 4; mt++)
        #pragma unroll
        for (int nt = 0; nt < 4; nt++)
            #pragma unroll
            for (int q = 0; q < 4; q++) acc[mt][nt][q] = 0.f;

    load_chunk(sbase, 0, A, W, row0, col0, 0, tid);

    for (int c = 0; c < NC; c++) {
        if (c + 1 < NC) {
            load_chunk(sbase, (c + 1) & 1, A, W, row0, col0, (c + 1) * BK, tid);
            cp_wait<1>();
        } else {
            cp_wait<0>();
        }
        __syncthreads();

        const float* As = (const float*)(smem + (c & 1) * STAGE_BYTES);
        const float* Ws = (const float*)(smem + (c & 1) * STAGE_BYTES + HALF_OFF);

        #pragma unroll
        for (int ks = 0; ks < 4; ks++) {
            const int k0 = ks * 8;
            uint32_t af[4][4], bf[4][2];
            #pragma unroll
            for (int mt = 0; mt < 4; mt++) {
                int row = wr * 64 + mt * 16;
                af[mt][0] = f2tf32(As[(row + g) * LDA + k0 + tg]);
                af[mt][1] = f2tf32(As[(row + g + 8) * LDA + k0 + tg]);
                af[mt][2] = f2tf32(As[(row + g) * LDA + k0 + tg + 4]);
                af[mt][3] = f2tf32(As[(row + g + 8) * LDA + k0 + tg + 4]);
            }
            #pragma unroll
            for (int nt = 0; nt < 4; nt++) {
                int col = wc * 32 + nt * 8;
                bf[nt][0] = f2tf32(Ws[(col + g) * LDA + k0 + tg]);
                bf[nt][1] = f2tf32(Ws[(col + g) * LDA + k0 + tg + 4]);
            }
            #pragma unroll
            for (int mt = 0; mt < 4; mt++)
                #pragma unroll
                for (int nt = 0; nt < 4; nt++)
                    mma_tf32(acc[mt][nt], af[mt], bf[nt]);
        }
        __syncthreads();
    }

    // Epilogue: direct fp32 global writes (float2 per fragment row)
    #pragma unroll
    for (int mt = 0; mt < 4; mt++) {
        int row = row0 + wr * 64 + mt * 16 + g;
        #pragma unroll
        for (int nt = 0; nt < 4; nt++) {
            int col = col0 + wc * 32 + nt * 8 + 2 * tg;
            *reinterpret_cast<float2*>(&C[(size_t)row * Dm + col]) =
                make_float2(acc[mt][nt][0], acc[mt][nt][1]);
            *reinterpret_cast<float2*>(&C[(size_t)(row + 8) * Dm + col]) =
                make_float2(acc[mt][nt][2], acc[mt][nt][3]);
        }
    }
}

// ---------------------------------------------------------------------------
// Flash attention (causal), fp32 — unchanged (next round's target).
// ---------------------------------------------------------------------------
#define BQ  64
#define BKV 32

__global__ __launch_bounds__(256) void flash_attn()
{
    const int qt = blockIdx.x;
    const int bh = blockIdx.y;
    const int b  = bh / Hh;
    const int h  = bh % Hh;
    const int q0 = qt * BQ;

    const size_t base = (size_t)b * Sq * Dm + (size_t)h * HD;
    const float* Qp = g_xq + base;
    const float* Kp = g_xk + base;
    const float* Vp = g_xv + base;
    float*       Op = g_ao + base;

    __shared__ float Qs[BQ][HD + 1];
    __shared__ float Ks[BKV][HD + 1];
    __shared__ float Vs[BKV][HD + 1];
    __shared__ float Ss[BQ][BKV + 1];
    __shared__ float row_m[BQ], row_l[BQ], row_sc[BQ];

    const int tid = threadIdx.x;
    const int tx = tid & 15;
    const int ty = tid >> 4;

    #pragma unroll
    for (int p = 0; p < 4; p++) {
        int idx = tid + p * 256;
        int r   = idx >> 4;
        int c4  = idx & 15;
        float4 v = *reinterpret_cast<const float4*>(
            &Qp[(size_t)(q0 + r) * Dm + c4 * 4]);
        Qs[r][c4 * 4 + 0] = v.x;
        Qs[r][c4 * 4 + 1] = v.y;
        Qs[r][c4 * 4 + 2] = v.z;
        Qs[r][c4 * 4 + 3] = v.w;
    }
    if (tid < BQ) { row_m[tid] = -INFINITY; row_l[tid] = 0.f; }

    float o[4][4];
    #pragma unroll
    for (int i = 0; i < 4; i++)
        #pragma unroll
        for (int j = 0; j < 4; j++) o[i][j] = 0.f;

    const int ntiles = 2 * qt + 2;
    for (int jt = 0; jt < ntiles; jt++) {
        __syncthreads();

        #pragma unroll
        for (int p = 0; p < 2; p++) {
            int idx = tid + p * 256;
            int r   = idx >> 4;
            int c4  = idx & 15;
            size_t off = (size_t)(jt * BKV + r) * Dm + c4 * 4;
            float4 vk = *reinterpret_cast<const float4*>(&Kp[off]);
            Ks[r][c4 * 4 + 0] = vk.x; Ks[r][c4 * 4 + 1] = vk.y;
            Ks[r][c4 * 4 + 2] = vk.z; Ks[r][c4 * 4 + 3] = vk.w;
            float4 vv = *reinterpret_cast<const float4*>(&Vp[off]);
            Vs[r][c4 * 4 + 0] = vv.x; Vs[r][c4 * 4 + 1] = vv.y;
            Vs[r][c4 * 4 + 2] = vv.z; Vs[r][c4 * 4 + 3] = vv.w;
        }
        __syncthreads();

        float s[4][2];
        #pragma unroll
        for (int i = 0; i < 4; i++) { s[i][0] = 0.f; s[i][1] = 0.f; }
        #pragma unroll
        for (int d = 0; d < HD; d++) {
            float a0 = Qs[ty][d], a1 = Qs[ty + 16][d];
            float a2 = Qs[ty + 32][d], a3 = Qs[ty + 48][d];
            float b0 = Ks[tx][d], b1 = Ks[tx + 16][d];
            s[0][0] = fmaf(a0, b0, s[0][0]); s[0][1] = fmaf(a0, b1, s[0][1]);
            s[1][0] = fmaf(a1, b0, s[1][0]); s[1][1] = fmaf(a1, b1, s[1][1]);
            s[2][0] = fmaf(a2, b0, s[2][0]); s[2][1] = fmaf(a2, b1, s[2][1]);
            s[3][0] = fmaf(a3, b0, s[3][0]); s[3][1] = fmaf(a3, b1, s[3][1]);
        }
        const float smul = 0.125f;
        #pragma unroll
        for (int i = 0; i < 4; i++) {
            int r = ty + 16 * i;
            #pragma unroll
            for (int jj = 0; jj < 2; jj++) {
                int c = tx + 16 * jj;
                float val = s[i][jj] * smul;
                if (jt * BKV + c > q0 + r) val = -INFINITY;
                Ss[r][c] = val;
            }
        }
        __syncthreads();

        if (tid < BQ) {
            int r = tid;
            float m_old = row_m[r];
            float m = m_old;
            #pragma unroll
            for (int c = 0; c < BKV; c++) m = fmaxf(m, Ss[r][c]);
            float sc = __expf(m_old - m);
            float l = row_l[r] * sc;
            #pragma unroll
            for (int c = 0; c < BKV; c++) {
                float pv = __expf(Ss[r][c] - m);
                Ss[r][c] = pv;
                l += pv;
            }
            row_m[r] = m; row_l[r] = l; row_sc[r] = sc;
        }
        __syncthreads();

        #pragma unroll
        for (int i = 0; i < 4; i++) {
            float sc = row_sc[ty + 16 * i];
            #pragma unroll
            for (int j = 0; j < 4; j++) o[i][j] *= sc;
        }
        #pragma unroll
        for (int k = 0; k < BKV; k++) {
            float p0 = Ss[ty][k], p1 = Ss[ty + 16][k];
            float p2 = Ss[ty + 32][k], p3 = Ss[ty + 48][k];
            float v0 = Vs[k][tx], v1 = Vs[k][tx + 16];
            float v2 = Vs[k][tx + 32], v3 = Vs[k][tx + 48];
            o[0][0] = fmaf(p0, v0, o[0][0]); o[0][1] = fmaf(p0, v1, o[0][1]);
            o[0][2] = fmaf(p0, v2, o[0][2]); o[0][3] = fmaf(p0, v3, o[0][3]);
            o[1][0] = fmaf(p1, v0, o[1][0]); o[1][1] = fmaf(p1, v1, o[1][1]);
            o[1][2] = fmaf(p1, v2, o[1][2]); o[1][3] = fmaf(p1, v3, o[1][3]);
            o[2][0] = fmaf(p2, v0, o[2][0]); o[2][1] = fmaf(p2, v1, o[2][1]);
            o[2][2] = fmaf(p2, v2, o[2][2]); o[2][3] = fmaf(p2, v3, o[2][3]);
            o[3][0] = fmaf(p3, v0, o[3][0]); o[3][1] = fmaf(p3, v1, o[3][1]);
            o[3][2] = fmaf(p3, v2, o[3][2]); o[3][3] = fmaf(p3, v3, o[3][3]);
        }
    }

    #pragma unroll
    for (int i = 0; i < 4; i++) {
        int r = ty + 16 * i;
        float inv_l = 1.f / row_l[r];
        #pragma unroll
        for (int j = 0; j < 4; j++) {
            Op[(size_t)(q0 + r) * Dm + tx + 16 * j] = o[i][j] * inv_l;
        }
    }
}

// ---------------------------------------------------------------------------
// Launch
// ---------------------------------------------------------------------------
extern "C" void kernel_launch(void* const* d_in, const int* in_sizes, int n_in,
                              void* d_out, int out_size)
{
    const float* q  = (const float*)d_in[0];
    const float* k  = (const float*)d_in[1];
    const float* v  = (const float*)d_in[2];
    const float* wq = (const float*)d_in[3];
    const float* wk = (const float*)d_in[4];
    const float* wv = (const float*)d_in[5];
    const float* wo = (const float*)d_in[6];
    float* out = (float*)d_out;

    cudaFuncSetAttribute(gemm_tc, cudaFuncAttributeMaxDynamicSharedMemorySize,
                         GSMEM);

    dim3 ggrid(Dm / 128, MTOT / 128, 1);   // (8, 64)
    gemm_tc<<<ggrid, 256, GSMEM>>>(q, wq, nullptr, 0, 1);
    gemm_tc<<<ggrid, 256, GSMEM>>>(k, wk, nullptr, 0, 2);
    gemm_tc<<<ggrid, 256, GSMEM>>>(v, wv, nullptr, 0, 3);

    dim3 agrid(Sq / BQ, Bsz * Hh, 1);      // (32, 64)
    flash_attn<<<agrid, 256>>>();

    gemm_tc<<<ggrid, 256, GSMEM>>>(nullptr, wo, out, 1, 0);
}

// round 5
// speedup vs baseline: 3.5391x; 2.0183x over previous
#include <cuda_runtime.h>
#include <cstdint>
#include <math.h>

// Problem constants
#define Bsz 4
#define Sq  2048
#define Dm  1024
#define Hh  16
#define HD  64
#define MTOT (Bsz * Sq)   // 8192

// Scratch (device globals — no allocation allowed)
__device__ float g_xq[(size_t)MTOT * Dm];
__device__ float g_xk[(size_t)MTOT * Dm];
__device__ float g_xv[(size_t)MTOT * Dm];
__device__ float g_ao[(size_t)MTOT * Dm];

// ===========================================================================
// Helpers: cp.async + tf32 mma.sync (sm_80+ PTX — valid on plain sm_103)
// ===========================================================================
__device__ __forceinline__ uint32_t smem_u32(const void* p) {
    uint32_t a;
    asm("{ .reg .u64 t; cvta.to.shared.u64 t, %1; cvt.u32.u64 %0, t; }"
        : "=r"(a) : "l"(p));
    return a;
}

__device__ __forceinline__ void cp16(uint32_t dst, const void* src) {
    asm volatile("cp.async.cg.shared.global [%0], [%1], 16;"
                 :: "r"(dst), "l"(src));
}
__device__ __forceinline__ void cp_commit() {
    asm volatile("cp.async.commit_group;" ::: "memory");
}
template<int N> __device__ __forceinline__ void cp_wait() {
    asm volatile("cp.async.wait_group %0;" :: "n"(N) : "memory");
}

__device__ __forceinline__ uint32_t f2tf32(float v) {
    uint32_t r;
    asm("cvt.rna.tf32.f32 %0, %1;" : "=r"(r) : "f"(v));
    return r;
}

// D(16x8) += A(16x8) * B(8x8), tf32 inputs, fp32 accumulate
__device__ __forceinline__ void mma_tf32(float* d, const uint32_t* a,
                                         const uint32_t* b) {
    asm volatile(
        "mma.sync.aligned.m16n8k8.row.col.f32.tf32.tf32.f32 "
        "{%0,%1,%2,%3}, {%4,%5,%6,%7}, {%8,%9}, {%0,%1,%2,%3};"
        : "+f"(d[0]), "+f"(d[1]), "+f"(d[2]), "+f"(d[3])
        : "r"(a[0]), "r"(a[1]), "r"(a[2]), "r"(a[3]),
          "r"(b[0]), "r"(b[1]));
}

// ===========================================================================
// Tensor-core GEMM: C[m,n] = sum_k A[m,k] * W[n,k]  (M=8192, N=K=1024)
// 128x128 CTA tile, BK=32, 2-stage cp.async double buffer.
// ===========================================================================
#define BK 32
#define NC (Dm / BK)              // 32 chunks
#define LDA 36
#define HALF_OFF (128 * LDA * 4)
#define STAGE_BYTES (2 * 128 * LDA * 4)   // 36864
#define GSMEM (2 * STAGE_BYTES)           // 73728

__device__ __forceinline__ void load_chunk(uint32_t sbase, int stage,
                                           const float* A, const float* W,
                                           int row0, int col0, int kb, int tid) {
    uint32_t a_st = sbase + stage * STAGE_BYTES;
    uint32_t w_st = a_st + HALF_OFF;
    #pragma unroll
    for (int p = 0; p < 4; p++) {
        int idx = tid + p * 256;
        int r  = idx >> 3;
        int cq = idx & 7;
        uint32_t d = (uint32_t)(r * (LDA * 4) + cq * 16);
        cp16(a_st + d, A + (size_t)(row0 + r) * Dm + kb + cq * 4);
        cp16(w_st + d, W + (size_t)(col0 + r) * Dm + kb + cq * 4);
    }
    cp_commit();
}

__global__ __launch_bounds__(256) void gemm_tc(const float* __restrict__ Ap,
                                               const float* __restrict__ W,
                                               float* __restrict__ Cp,
                                               int asel, int csel)
{
    extern __shared__ char smem[];
    uint32_t sbase = smem_u32(smem);
    const float* A = asel ? g_ao : Ap;
    float* C = (csel == 0) ? Cp : (csel == 1 ? g_xq : (csel == 2 ? g_xk : g_xv));

    const int tid = threadIdx.x;
    const int wid = tid >> 5;
    const int lid = tid & 31;
    const int g   = lid >> 2;
    const int tg  = lid & 3;
    const int wr  = wid >> 2;
    const int wc  = wid & 3;
    const int row0 = blockIdx.y * 128;
    const int col0 = blockIdx.x * 128;

    float acc[4][4][4];
    #pragma unroll
    for (int mt = 0; mt < 4; mt++)
        #pragma unroll
        for (int nt = 0; nt < 4; nt++)
            #pragma unroll
            for (int q = 0; q < 4; q++) acc[mt][nt][q] = 0.f;

    load_chunk(sbase, 0, A, W, row0, col0, 0, tid);

    for (int c = 0; c < NC; c++) {
        if (c + 1 < NC) {
            load_chunk(sbase, (c + 1) & 1, A, W, row0, col0, (c + 1) * BK, tid);
            cp_wait<1>();
        } else {
            cp_wait<0>();
        }
        __syncthreads();

        const float* As = (const float*)(smem + (c & 1) * STAGE_BYTES);
        const float* Ws = (const float*)(smem + (c & 1) * STAGE_BYTES + HALF_OFF);

        #pragma unroll
        for (int ks = 0; ks < 4; ks++) {
            const int k0 = ks * 8;
            uint32_t af[4][4], bf[4][2];
            #pragma unroll
            for (int mt = 0; mt < 4; mt++) {
                int row = wr * 64 + mt * 16;
                af[mt][0] = f2tf32(As[(row + g) * LDA + k0 + tg]);
                af[mt][1] = f2tf32(As[(row + g + 8) * LDA + k0 + tg]);
                af[mt][2] = f2tf32(As[(row + g) * LDA + k0 + tg + 4]);
                af[mt][3] = f2tf32(As[(row + g + 8) * LDA + k0 + tg + 4]);
            }
            #pragma unroll
            for (int nt = 0; nt < 4; nt++) {
                int col = wc * 32 + nt * 8;
                bf[nt][0] = f2tf32(Ws[(col + g) * LDA + k0 + tg]);
                bf[nt][1] = f2tf32(Ws[(col + g) * LDA + k0 + tg + 4]);
            }
            #pragma unroll
            for (int mt = 0; mt < 4; mt++)
                #pragma unroll
                for (int nt = 0; nt < 4; nt++)
                    mma_tf32(acc[mt][nt], af[mt], bf[nt]);
        }
        __syncthreads();
    }

    #pragma unroll
    for (int mt = 0; mt < 4; mt++) {
        int row = row0 + wr * 64 + mt * 16 + g;
        #pragma unroll
        for (int nt = 0; nt < 4; nt++) {
            int col = col0 + wc * 32 + nt * 8 + 2 * tg;
            *reinterpret_cast<float2*>(&C[(size_t)row * Dm + col]) =
                make_float2(acc[mt][nt][0], acc[mt][nt][1]);
            *reinterpret_cast<float2*>(&C[(size_t)(row + 8) * Dm + col]) =
                make_float2(acc[mt][nt][2], acc[mt][nt][3]);
        }
    }
}

// ===========================================================================
// Flash attention (causal) on tensor cores, tf32 mma.sync.
// BQ=128 (8 warps x 16 rows), BKV=64, HD=64, 256 threads.
// ===========================================================================
#define LDK 68                        // floats per SMEM row (64 + 4 pad)
#define KS_OFF 0                      // K tile   [64][LDK]
#define VT_OFF (64 * LDK * 4)         // V^T tile [64][LDK]  (hd, kv)
#define PS_OFF (2 * 64 * LDK * 4)     // P / Q staging [128][LDK]
#define AT_SMEM (PS_OFF + 128 * LDK * 4)   // 69632 bytes

__global__ __launch_bounds__(256) void flash_attn_tc()
{
    extern __shared__ char smem[];
    float* Ks = (float*)(smem + KS_OFF);
    float* Vt = (float*)(smem + VT_OFF);
    float* Ps = (float*)(smem + PS_OFF);

    const int qt = blockIdx.x;           // 0..15
    const int bh = blockIdx.y;           // 0..63
    const int b  = bh >> 4;
    const int h  = bh & 15;
    const int q0 = qt * 128;

    const size_t base = (size_t)b * Sq * Dm + (size_t)h * HD;
    const float* Qp = g_xq + base;
    const float* Kp = g_xk + base;
    const float* Vp = g_xv + base;
    float*       Op = g_ao + base;

    const int tid = threadIdx.x;
    const int wid = tid >> 5;
    const int lid = tid & 31;
    const int g   = lid >> 2;
    const int tg  = lid & 3;
    const int wrow = wid * 16;           // warp's Q-row offset in tile

    // ---- Stage Q (scaled by 1/8) into Ps, then load fragments -------------
    #pragma unroll
    for (int p = 0; p < 8; p++) {
        int idx = tid + p * 256;         // 0..2047
        int r   = idx >> 4;              // 0..127
        int c4  = idx & 15;
        float4 v = *reinterpret_cast<const float4*>(
            &Qp[(size_t)(q0 + r) * Dm + c4 * 4]);
        v.x *= 0.125f; v.y *= 0.125f; v.z *= 0.125f; v.w *= 0.125f;
        *reinterpret_cast<float4*>(&Ps[r * LDK + c4 * 4]) = v;
    }
    __syncthreads();

    uint32_t qf[8][4];
    #pragma unroll
    for (int kt = 0; kt < 8; kt++) {
        int k0 = kt * 8;
        qf[kt][0] = f2tf32(Ps[(wrow + g) * LDK + k0 + tg]);
        qf[kt][1] = f2tf32(Ps[(wrow + g + 8) * LDK + k0 + tg]);
        qf[kt][2] = f2tf32(Ps[(wrow + g) * LDK + k0 + tg + 4]);
        qf[kt][3] = f2tf32(Ps[(wrow + g + 8) * LDK + k0 + tg + 4]);
    }
    // No sync needed: each warp reads only its own 16 rows for Q and later
    // writes P only to those same rows.

    float m0 = -1e30f, m1 = -1e30f, l0 = 0.f, l1 = 0.f;
    float o[8][4];
    #pragma unroll
    for (int nt = 0; nt < 8; nt++)
        #pragma unroll
        for (int q = 0; q < 4; q++) o[nt][q] = 0.f;

    const int row_g  = q0 + wrow + g;
    const int row_g8 = row_g + 8;
    const int ntl = 2 * qt + 2;

    for (int jt = 0; jt < ntl; jt++) {
        __syncthreads();   // K/V/P tiles free for rewrite

        // Load K tile [64 kv][64 hd], coalesced
        #pragma unroll
        for (int p = 0; p < 4; p++) {
            int idx = tid + p * 256;     // 0..1023
            int r   = idx >> 4;          // 0..63
            int c4  = idx & 15;
            float4 v = *reinterpret_cast<const float4*>(
                &Kp[(size_t)(jt * 64 + r) * Dm + c4 * 4]);
            *reinterpret_cast<float4*>(&Ks[r * LDK + c4 * 4]) = v;
        }
        // Load V transposed into Vt[hd][kv] (r=idx&63 keeps STS conflict-free)
        #pragma unroll
        for (int p = 0; p < 4; p++) {
            int idx = tid + p * 256;
            int r   = idx & 63;          // kv row
            int c4  = idx >> 6;          // 0..15 hd group
            float4 v = *reinterpret_cast<const float4*>(
                &Vp[(size_t)(jt * 64 + r) * Dm + c4 * 4]);
            Vt[(c4 * 4 + 0) * LDK + r] = v.x;
            Vt[(c4 * 4 + 1) * LDK + r] = v.y;
            Vt[(c4 * 4 + 2) * LDK + r] = v.z;
            Vt[(c4 * 4 + 3) * LDK + r] = v.w;
        }
        __syncthreads();

        // Fully-masked warp rows: skip compute (still hit barriers)
        if (jt * 64 > q0 + wrow + 15) continue;

        // ---- S = Q K^T -----------------------------------------------------
        float sacc[8][4];
        #pragma unroll
        for (int nt = 0; nt < 8; nt++)
            #pragma unroll
            for (int q = 0; q < 4; q++) sacc[nt][q] = 0.f;

        #pragma unroll
        for (int nt = 0; nt < 8; nt++) {
            #pragma unroll
            for (int kt = 0; kt < 8; kt++) {
                int k0 = kt * 8;
                uint32_t bf[2];
                bf[0] = f2tf32(Ks[(nt * 8 + g) * LDK + k0 + tg]);
                bf[1] = f2tf32(Ks[(nt * 8 + g) * LDK + k0 + tg + 4]);
                mma_tf32(sacc[nt], qf[kt], bf);
            }
        }

        // ---- Causal mask (diagonal tiles only) -----------------------------
        if (jt >= 2 * qt) {
            #pragma unroll
            for (int nt = 0; nt < 8; nt++) {
                int cb = jt * 64 + nt * 8 + 2 * tg;
                if (cb     > row_g ) sacc[nt][0] = -1e30f;
                if (cb + 1 > row_g ) sacc[nt][1] = -1e30f;
                if (cb     > row_g8) sacc[nt][2] = -1e30f;
                if (cb + 1 > row_g8) sacc[nt][3] = -1e30f;
            }
        }

        // ---- Online softmax (register + shfl) ------------------------------
        float mn0 = m0, mn1 = m1;
        #pragma unroll
        for (int nt = 0; nt < 8; nt++) {
            mn0 = fmaxf(mn0, fmaxf(sacc[nt][0], sacc[nt][1]));
            mn1 = fmaxf(mn1, fmaxf(sacc[nt][2], sacc[nt][3]));
        }
        mn0 = fmaxf(mn0, __shfl_xor_sync(0xffffffffu, mn0, 1));
        mn0 = fmaxf(mn0, __shfl_xor_sync(0xffffffffu, mn0, 2));
        mn1 = fmaxf(mn1, __shfl_xor_sync(0xffffffffu, mn1, 1));
        mn1 = fmaxf(mn1, __shfl_xor_sync(0xffffffffu, mn1, 2));

        float sc0 = __expf(m0 - mn0);
        float sc1 = __expf(m1 - mn1);
        m0 = mn0; m1 = mn1;

        float ls0 = 0.f, ls1 = 0.f;
        #pragma unroll
        for (int nt = 0; nt < 8; nt++) {
            float p0 = __expf(sacc[nt][0] - mn0);
            float p1 = __expf(sacc[nt][1] - mn0);
            float p2 = __expf(sacc[nt][2] - mn1);
            float p3 = __expf(sacc[nt][3] - mn1);
            ls0 += p0 + p1;
            ls1 += p2 + p3;
            int col = nt * 8 + 2 * tg;
            *reinterpret_cast<float2*>(&Ps[(wrow + g) * LDK + col]) =
                make_float2(p0, p1);
            *reinterpret_cast<float2*>(&Ps[(wrow + g + 8) * LDK + col]) =
                make_float2(p2, p3);
        }
        ls0 += __shfl_xor_sync(0xffffffffu, ls0, 1);
        ls0 += __shfl_xor_sync(0xffffffffu, ls0, 2);
        ls1 += __shfl_xor_sync(0xffffffffu, ls1, 1);
        ls1 += __shfl_xor_sync(0xffffffffu, ls1, 2);
        l0 = l0 * sc0 + ls0;
        l1 = l1 * sc1 + ls1;

        #pragma unroll
        for (int nt = 0; nt < 8; nt++) {
            o[nt][0] *= sc0; o[nt][1] *= sc0;
            o[nt][2] *= sc1; o[nt][3] *= sc1;
        }
        __syncwarp();

        // ---- O += P V  (A = warp-private Ps rows, B = Vt) ------------------
        #pragma unroll
        for (int kt = 0; kt < 8; kt++) {
            int k0 = kt * 8;
            uint32_t ap[4];
            ap[0] = f2tf32(Ps[(wrow + g) * LDK + k0 + tg]);
            ap[1] = f2tf32(Ps[(wrow + g + 8) * LDK + k0 + tg]);
            ap[2] = f2tf32(Ps[(wrow + g) * LDK + k0 + tg + 4]);
            ap[3] = f2tf32(Ps[(wrow + g + 8) * LDK + k0 + tg + 4]);
            #pragma unroll
            for (int nt = 0; nt < 8; nt++) {
                uint32_t bf[2];
                bf[0] = f2tf32(Vt[(nt * 8 + g) * LDK + k0 + tg]);
                bf[1] = f2tf32(Vt[(nt * 8 + g) * LDK + k0 + tg + 4]);
                mma_tf32(o[nt], ap, bf);
            }
        }
    }

    // ---- Epilogue: normalize and write O ----------------------------------
    float il0 = 1.f / l0, il1 = 1.f / l1;
    #pragma unroll
    for (int nt = 0; nt < 8; nt++) {
        int col = nt * 8 + 2 * tg;
        *reinterpret_cast<float2*>(&Op[(size_t)(row_g) * Dm + col]) =
            make_float2(o[nt][0] * il0, o[nt][1] * il0);
        *reinterpret_cast<float2*>(&Op[(size_t)(row_g8) * Dm + col]) =
            make_float2(o[nt][2] * il1, o[nt][3] * il1);
    }
}

// ---------------------------------------------------------------------------
// Launch
// ---------------------------------------------------------------------------
extern "C" void kernel_launch(void* const* d_in, const int* in_sizes, int n_in,
                              void* d_out, int out_size)
{
    const float* q  = (const float*)d_in[0];
    const float* k  = (const float*)d_in[1];
    const float* v  = (const float*)d_in[2];
    const float* wq = (const float*)d_in[3];
    const float* wk = (const float*)d_in[4];
    const float* wv = (const float*)d_in[5];
    const float* wo = (const float*)d_in[6];
    float* out = (float*)d_out;

    cudaFuncSetAttribute(gemm_tc, cudaFuncAttributeMaxDynamicSharedMemorySize,
                         GSMEM);
    cudaFuncSetAttribute(flash_attn_tc,
                         cudaFuncAttributeMaxDynamicSharedMemorySize, AT_SMEM);

    dim3 ggrid(Dm / 128, MTOT / 128, 1);   // (8, 64)
    gemm_tc<<<ggrid, 256, GSMEM>>>(q, wq, nullptr, 0, 1);
    gemm_tc<<<ggrid, 256, GSMEM>>>(k, wk, nullptr, 0, 2);
    gemm_tc<<<ggrid, 256, GSMEM>>>(v, wv, nullptr, 0, 3);

    dim3 agrid(Sq / 128, Bsz * Hh, 1);     // (16, 64)
    flash_attn_tc<<<agrid, 256, AT_SMEM>>>();

    gemm_tc<<<ggrid, 256, GSMEM>>>(nullptr, wo, out, 1, 0);
}

// round 6
// speedup vs baseline: 3.7156x; 1.0499x over previous
#include <cuda_runtime.h>
#include <cstdint>
#include <math.h>

// Problem constants
#define Bsz 4
#define Sq  2048
#define Dm  1024
#define Hh  16
#define HD  64
#define MTOT (Bsz * Sq)   // 8192
#define NEL ((size_t)MTOT * Dm)   // 8M
#define WEL ((size_t)Dm * Dm)     // 1M

// Scratch (device globals — no allocation allowed). All tf32-bit uint32.
__device__ uint32_t g_qc[NEL];        // tf32(0.125 * q)
__device__ uint32_t g_kc[NEL];        // tf32(k)
__device__ uint32_t g_vc[NEL];        // tf32(v)
__device__ uint32_t g_wc[4 * WEL];    // tf32(wq,wk,wv,wo)
__device__ uint32_t g_xq[NEL];        // tf32(Q proj out)
__device__ uint32_t g_xk[NEL];
__device__ uint32_t g_xv[NEL];
__device__ uint32_t g_ao[NEL];        // tf32(attention out)

// ===========================================================================
// Helpers
// ===========================================================================
__device__ __forceinline__ uint32_t smem_u32(const void* p) {
    uint32_t a;
    asm("{ .reg .u64 t; cvta.to.shared.u64 t, %1; cvt.u32.u64 %0, t; }"
        : "=r"(a) : "l"(p));
    return a;
}
__device__ __forceinline__ void cp16(uint32_t dst, const void* src) {
    asm volatile("cp.async.cg.shared.global [%0], [%1], 16;"
                 :: "r"(dst), "l"(src));
}
__device__ __forceinline__ void cp_commit() {
    asm volatile("cp.async.commit_group;" ::: "memory");
}
template<int N> __device__ __forceinline__ void cp_wait() {
    asm volatile("cp.async.wait_group %0;" :: "n"(N) : "memory");
}
__device__ __forceinline__ uint32_t f2tf32(float v) {
    uint32_t r;
    asm("cvt.rna.tf32.f32 %0, %1;" : "=r"(r) : "f"(v));
    return r;
}
__device__ __forceinline__ void mma_tf32(float* d, const uint32_t* a,
                                         const uint32_t* b) {
    asm volatile(
        "mma.sync.aligned.m16n8k8.row.col.f32.tf32.tf32.f32 "
        "{%0,%1,%2,%3}, {%4,%5,%6,%7}, {%8,%9}, {%0,%1,%2,%3};"
        : "+f"(d[0]), "+f"(d[1]), "+f"(d[2]), "+f"(d[3])
        : "r"(a[0]), "r"(a[1]), "r"(a[2]), "r"(a[3]),
          "r"(b[0]), "r"(b[1]));
}

// ===========================================================================
// Pre-convert fp32 -> tf32 bits (vectorized). dsel: 0=qc 1=kc 2=vc 3..6=wc[j]
// ===========================================================================
__global__ __launch_bounds__(256) void conv_tf32(const float* __restrict__ src,
                                                 int dsel, float scale, int n4)
{
    int i = blockIdx.x * 256 + threadIdx.x;
    if (i >= n4) return;
    uint32_t* dst = (dsel == 0) ? g_qc : (dsel == 1) ? g_kc : (dsel == 2) ? g_vc
                   : g_wc + (size_t)(dsel - 3) * WEL;
    float4 v = reinterpret_cast<const float4*>(src)[i];
    uint4 u;
    u.x = f2tf32(v.x * scale);
    u.y = f2tf32(v.y * scale);
    u.z = f2tf32(v.z * scale);
    u.w = f2tf32(v.w * scale);
    reinterpret_cast<uint4*>(dst)[i] = u;
}

// ===========================================================================
// Tensor-core GEMM on pre-converted tf32 operands.
// C[m,n] = sum_k A[m,k]*W[n,k]; 128x128 tile, BK=32, double buffer.
// ===========================================================================
#define BK 32
#define NC (Dm / BK)
#define LDA 36
#define HALF_OFF (128 * LDA * 4)
#define STAGE_BYTES (2 * 128 * LDA * 4)   // 36864
#define GSMEM (2 * STAGE_BYTES)           // 73728

__device__ __forceinline__ void load_chunk(uint32_t sbase, int stage,
                                           const uint32_t* A, const uint32_t* W,
                                           int row0, int col0, int kb, int tid) {
    uint32_t a_st = sbase + stage * STAGE_BYTES;
    uint32_t w_st = a_st + HALF_OFF;
    #pragma unroll
    for (int p = 0; p < 4; p++) {
        int idx = tid + p * 256;
        int r  = idx >> 3;
        int cq = idx & 7;
        uint32_t d = (uint32_t)(r * (LDA * 4) + cq * 16);
        cp16(a_st + d, A + (size_t)(row0 + r) * Dm + kb + cq * 4);
        cp16(w_st + d, W + (size_t)(col0 + r) * Dm + kb + cq * 4);
    }
    cp_commit();
}

// asel: 0=g_qc 1=g_kc 2=g_vc 3=g_ao ; wsel: 0..3 ;
// csel: 0 -> fp32 out to Cp, 1..3 -> tf32 bits to g_xq/g_xk/g_xv
__global__ __launch_bounds__(256) void gemm_tc(float* __restrict__ Cp,
                                               int asel, int wsel, int csel)
{
    extern __shared__ char smem[];
    uint32_t sbase = smem_u32(smem);
    const uint32_t* A = (asel == 0) ? g_qc : (asel == 1) ? g_kc
                       : (asel == 2) ? g_vc : g_ao;
    const uint32_t* W = g_wc + (size_t)wsel * WEL;
    uint32_t* Cu = (csel == 1) ? g_xq : (csel == 2) ? g_xk : g_xv;

    const int tid = threadIdx.x;
    const int wid = tid >> 5;
    const int lid = tid & 31;
    const int g   = lid >> 2;
    const int tg  = lid & 3;
    const int wr  = wid >> 2;
    const int wc  = wid & 3;
    const int row0 = blockIdx.y * 128;
    const int col0 = blockIdx.x * 128;

    float acc[4][4][4];
    #pragma unroll
    for (int mt = 0; mt < 4; mt++)
        #pragma unroll
        for (int nt = 0; nt < 4; nt++)
            #pragma unroll
            for (int q = 0; q < 4; q++) acc[mt][nt][q] = 0.f;

    load_chunk(sbase, 0, A, W, row0, col0, 0, tid);

    for (int c = 0; c < NC; c++) {
        if (c + 1 < NC) {
            load_chunk(sbase, (c + 1) & 1, A, W, row0, col0, (c + 1) * BK, tid);
            cp_wait<1>();
        } else {
            cp_wait<0>();
        }
        __syncthreads();

        const uint32_t* As = (const uint32_t*)(smem + (c & 1) * STAGE_BYTES);
        const uint32_t* Ws = (const uint32_t*)(smem + (c & 1) * STAGE_BYTES + HALF_OFF);

        #pragma unroll
        for (int ks = 0; ks < 4; ks++) {
            const int k0 = ks * 8;
            uint32_t af[4][4], bf[4][2];
            #pragma unroll
            for (int mt = 0; mt < 4; mt++) {
                int row = wr * 64 + mt * 16;
                af[mt][0] = As[(row + g) * LDA + k0 + tg];
                af[mt][1] = As[(row + g + 8) * LDA + k0 + tg];
                af[mt][2] = As[(row + g) * LDA + k0 + tg + 4];
                af[mt][3] = As[(row + g + 8) * LDA + k0 + tg + 4];
            }
            #pragma unroll
            for (int nt = 0; nt < 4; nt++) {
                int col = wc * 32 + nt * 8;
                bf[nt][0] = Ws[(col + g) * LDA + k0 + tg];
                bf[nt][1] = Ws[(col + g) * LDA + k0 + tg + 4];
            }
            #pragma unroll
            for (int mt = 0; mt < 4; mt++)
                #pragma unroll
                for (int nt = 0; nt < 4; nt++)
                    mma_tf32(acc[mt][nt], af[mt], bf[nt]);
        }
        __syncthreads();
    }

    #pragma unroll
    for (int mt = 0; mt < 4; mt++) {
        int row = row0 + wr * 64 + mt * 16 + g;
        #pragma unroll
        for (int nt = 0; nt < 4; nt++) {
            int col = col0 + wc * 32 + nt * 8 + 2 * tg;
            if (csel == 0) {
                *reinterpret_cast<float2*>(&Cp[(size_t)row * Dm + col]) =
                    make_float2(acc[mt][nt][0], acc[mt][nt][1]);
                *reinterpret_cast<float2*>(&Cp[(size_t)(row + 8) * Dm + col]) =
                    make_float2(acc[mt][nt][2], acc[mt][nt][3]);
            } else {
                uint2 u0 = make_uint2(f2tf32(acc[mt][nt][0]), f2tf32(acc[mt][nt][1]));
                uint2 u1 = make_uint2(f2tf32(acc[mt][nt][2]), f2tf32(acc[mt][nt][3]));
                *reinterpret_cast<uint2*>(&Cu[(size_t)row * Dm + col]) = u0;
                *reinterpret_cast<uint2*>(&Cu[(size_t)(row + 8) * Dm + col]) = u1;
            }
        }
    }
}

// ===========================================================================
// Flash attention (causal), tf32 mma.sync, zero in-loop conversions.
// BQ=128 (8 warps x 16 rows), BKV=64, HD=64, 256 threads.
// ===========================================================================
#define LDK 68
#define KS_OFF 0
#define VT_OFF (64 * LDK * 4)
#define PS_OFF (2 * 64 * LDK * 4)
#define AT_SMEM (PS_OFF + 128 * LDK * 4)   // 69632 bytes

__global__ __launch_bounds__(256) void flash_attn_tc()
{
    extern __shared__ char smem[];
    uint32_t* Ks = (uint32_t*)(smem + KS_OFF);
    uint32_t* Vt = (uint32_t*)(smem + VT_OFF);
    uint32_t* Ps = (uint32_t*)(smem + PS_OFF);

    const int qt = (gridDim.x - 1) - blockIdx.x;   // heavy tiles first
    const int bh = blockIdx.y;
    const int b  = bh >> 4;
    const int h  = bh & 15;
    const int q0 = qt * 128;

    const size_t base = (size_t)b * Sq * Dm + (size_t)h * HD;
    const uint32_t* Qp = g_xq + base;
    const uint32_t* Kp = g_xk + base;
    const uint32_t* Vp = g_xv + base;
    uint32_t*       Op = g_ao + base;

    const int tid = threadIdx.x;
    const int wid = tid >> 5;
    const int lid = tid & 31;
    const int g   = lid >> 2;
    const int tg  = lid & 3;
    const int wrow = wid * 16;

    // ---- Stage Q into Ps (raw tf32 bits), then load fragments -------------
    #pragma unroll
    for (int p = 0; p < 8; p++) {
        int idx = tid + p * 256;
        int r   = idx >> 4;
        int c4  = idx & 15;
        uint4 v = *reinterpret_cast<const uint4*>(
            &Qp[(size_t)(q0 + r) * Dm + c4 * 4]);
        *reinterpret_cast<uint4*>(&Ps[r * LDK + c4 * 4]) = v;
    }
    __syncthreads();

    uint32_t qf[8][4];
    #pragma unroll
    for (int kt = 0; kt < 8; kt++) {
        int k0 = kt * 8;
        qf[kt][0] = Ps[(wrow + g) * LDK + k0 + tg];
        qf[kt][1] = Ps[(wrow + g + 8) * LDK + k0 + tg];
        qf[kt][2] = Ps[(wrow + g) * LDK + k0 + tg + 4];
        qf[kt][3] = Ps[(wrow + g + 8) * LDK + k0 + tg + 4];
    }

    float m0 = -1e30f, m1 = -1e30f, l0 = 0.f, l1 = 0.f;
    float o[8][4];
    #pragma unroll
    for (int nt = 0; nt < 8; nt++)
        #pragma unroll
        for (int q = 0; q < 4; q++) o[nt][q] = 0.f;

    const int row_g  = q0 + wrow + g;
    const int row_g8 = row_g + 8;
    const int ntl = 2 * qt + 2;

    for (int jt = 0; jt < ntl; jt++) {
        __syncthreads();

        #pragma unroll
        for (int p = 0; p < 4; p++) {
            int idx = tid + p * 256;
            int r   = idx >> 4;
            int c4  = idx & 15;
            uint4 v = *reinterpret_cast<const uint4*>(
                &Kp[(size_t)(jt * 64 + r) * Dm + c4 * 4]);
            *reinterpret_cast<uint4*>(&Ks[r * LDK + c4 * 4]) = v;
        }
        #pragma unroll
        for (int p = 0; p < 4; p++) {
            int idx = tid + p * 256;
            int r   = idx & 63;
            int c4  = idx >> 6;
            uint4 v = *reinterpret_cast<const uint4*>(
                &Vp[(size_t)(jt * 64 + r) * Dm + c4 * 4]);
            Vt[(c4 * 4 + 0) * LDK + r] = v.x;
            Vt[(c4 * 4 + 1) * LDK + r] = v.y;
            Vt[(c4 * 4 + 2) * LDK + r] = v.z;
            Vt[(c4 * 4 + 3) * LDK + r] = v.w;
        }
        __syncthreads();

        if (jt * 64 > q0 + wrow + 15) continue;

        // ---- S = Q K^T ----
        float sacc[8][4];
        #pragma unroll
        for (int nt = 0; nt < 8; nt++)
            #pragma unroll
            for (int q = 0; q < 4; q++) sacc[nt][q] = 0.f;

        #pragma unroll
        for (int nt = 0; nt < 8; nt++) {
            #pragma unroll
            for (int kt = 0; kt < 8; kt++) {
                int k0 = kt * 8;
                uint32_t bf[2];
                bf[0] = Ks[(nt * 8 + g) * LDK + k0 + tg];
                bf[1] = Ks[(nt * 8 + g) * LDK + k0 + tg + 4];
                mma_tf32(sacc[nt], qf[kt], bf);
            }
        }

        // ---- Causal mask (diagonal tiles only) ----
        if (jt >= 2 * qt) {
            #pragma unroll
            for (int nt = 0; nt < 8; nt++) {
                int cb = jt * 64 + nt * 8 + 2 * tg;
                if (cb     > row_g ) sacc[nt][0] = -1e30f;
                if (cb + 1 > row_g ) sacc[nt][1] = -1e30f;
                if (cb     > row_g8) sacc[nt][2] = -1e30f;
                if (cb + 1 > row_g8) sacc[nt][3] = -1e30f;
            }
        }

        // ---- Online softmax (register + shfl) ----
        float mn0 = m0, mn1 = m1;
        #pragma unroll
        for (int nt = 0; nt < 8; nt++) {
            mn0 = fmaxf(mn0, fmaxf(sacc[nt][0], sacc[nt][1]));
            mn1 = fmaxf(mn1, fmaxf(sacc[nt][2], sacc[nt][3]));
        }
        mn0 = fmaxf(mn0, __shfl_xor_sync(0xffffffffu, mn0, 1));
        mn0 = fmaxf(mn0, __shfl_xor_sync(0xffffffffu, mn0, 2));
        mn1 = fmaxf(mn1, __shfl_xor_sync(0xffffffffu, mn1, 1));
        mn1 = fmaxf(mn1, __shfl_xor_sync(0xffffffffu, mn1, 2));

        float sc0 = __expf(m0 - mn0);
        float sc1 = __expf(m1 - mn1);
        m0 = mn0; m1 = mn1;

        float ls0 = 0.f, ls1 = 0.f;
        #pragma unroll
        for (int nt = 0; nt < 8; nt++) {
            float p0 = __expf(sacc[nt][0] - mn0);
            float p1 = __expf(sacc[nt][1] - mn0);
            float p2 = __expf(sacc[nt][2] - mn1);
            float p3 = __expf(sacc[nt][3] - mn1);
            ls0 += p0 + p1;
            ls1 += p2 + p3;
            int col = nt * 8 + 2 * tg;
            *reinterpret_cast<uint2*>(&Ps[(wrow + g) * LDK + col]) =
                make_uint2(f2tf32(p0), f2tf32(p1));
            *reinterpret_cast<uint2*>(&Ps[(wrow + g + 8) * LDK + col]) =
                make_uint2(f2tf32(p2), f2tf32(p3));
        }
        ls0 += __shfl_xor_sync(0xffffffffu, ls0, 1);
        ls0 += __shfl_xor_sync(0xffffffffu, ls0, 2);
        ls1 += __shfl_xor_sync(0xffffffffu, ls1, 1);
        ls1 += __shfl_xor_sync(0xffffffffu, ls1, 2);
        l0 = l0 * sc0 + ls0;
        l1 = l1 * sc1 + ls1;

        #pragma unroll
        for (int nt = 0; nt < 8; nt++) {
            o[nt][0] *= sc0; o[nt][1] *= sc0;
            o[nt][2] *= sc1; o[nt][3] *= sc1;
        }
        __syncwarp();

        // ---- O += P V ----
        #pragma unroll
        for (int kt = 0; kt < 8; kt++) {
            int k0 = kt * 8;
            uint32_t ap[4];
            ap[0] = Ps[(wrow + g) * LDK + k0 + tg];
            ap[1] = Ps[(wrow + g + 8) * LDK + k0 + tg];
            ap[2] = Ps[(wrow + g) * LDK + k0 + tg + 4];
            ap[3] = Ps[(wrow + g + 8) * LDK + k0 + tg + 4];
            #pragma unroll
            for (int nt = 0; nt < 8; nt++) {
                uint32_t bf[2];
                bf[0] = Vt[(nt * 8 + g) * LDK + k0 + tg];
                bf[1] = Vt[(nt * 8 + g) * LDK + k0 + tg + 4];
                mma_tf32(o[nt], ap, bf);
            }
        }
    }

    // ---- Epilogue: normalize, convert to tf32 bits, write ----
    float il0 = 1.f / l0, il1 = 1.f / l1;
    #pragma unroll
    for (int nt = 0; nt < 8; nt++) {
        int col = nt * 8 + 2 * tg;
        *reinterpret_cast<uint2*>(&Op[(size_t)(row_g) * Dm + col]) =
            make_uint2(f2tf32(o[nt][0] * il0), f2tf32(o[nt][1] * il0));
        *reinterpret_cast<uint2*>(&Op[(size_t)(row_g8) * Dm + col]) =
            make_uint2(f2tf32(o[nt][2] * il1), f2tf32(o[nt][3] * il1));
    }
}

// ---------------------------------------------------------------------------
// Launch: converts -> 3 projections -> attention -> output projection
// ---------------------------------------------------------------------------
extern "C" void kernel_launch(void* const* d_in, const int* in_sizes, int n_in,
                              void* d_out, int out_size)
{
    const float* q  = (const float*)d_in[0];
    const float* k  = (const float*)d_in[1];
    const float* v  = (const float*)d_in[2];
    const float* wq = (const float*)d_in[3];
    const float* wk = (const float*)d_in[4];
    const float* wv = (const float*)d_in[5];
    const float* wo = (const float*)d_in[6];
    float* out = (float*)d_out;

    cudaFuncSetAttribute(gemm_tc, cudaFuncAttributeMaxDynamicSharedMemorySize,
                         GSMEM);
    cudaFuncSetAttribute(flash_attn_tc,
                         cudaFuncAttributeMaxDynamicSharedMemorySize, AT_SMEM);

    const int n4i = (int)(NEL / 4);   // input tensors, float4 units
    const int n4w = (int)(WEL / 4);   // weights
    conv_tf32<<<(n4i + 255) / 256, 256>>>(q,  0, 0.125f, n4i);  // fold 1/sqrt(64)
    conv_tf32<<<(n4i + 255) / 256, 256>>>(k,  1, 1.f, n4i);
    conv_tf32<<<(n4i + 255) / 256, 256>>>(v,  2, 1.f, n4i);
    conv_tf32<<<(n4w + 255) / 256, 256>>>(wq, 3, 1.f, n4w);
    conv_tf32<<<(n4w + 255) / 256, 256>>>(wk, 4, 1.f, n4w);
    conv_tf32<<<(n4w + 255) / 256, 256>>>(wv, 5, 1.f, n4w);
    conv_tf32<<<(n4w + 255) / 256, 256>>>(wo, 6, 1.f, n4w);

    dim3 ggrid(Dm / 128, MTOT / 128, 1);   // (8, 64)
    gemm_tc<<<ggrid, 256, GSMEM>>>(nullptr, 0, 0, 1);   // Q proj
    gemm_tc<<<ggrid, 256, GSMEM>>>(nullptr, 1, 1, 2);   // K proj
    gemm_tc<<<ggrid, 256, GSMEM>>>(nullptr, 2, 2, 3);   // V proj

    dim3 agrid(Sq / 128, Bsz * Hh, 1);     // (16, 64)
    flash_attn_tc<<<agrid, 256, AT_SMEM>>>();

    gemm_tc<<<ggrid, 256, GSMEM>>>(out, 3, 3, 0);       // O proj -> fp32 out
}

// round 7
// speedup vs baseline: 4.3923x; 1.1821x over previous
#include <cuda_runtime.h>
#include <cstdint>
#include <math.h>

// Problem constants
#define Bsz 4
#define Sq  2048
#define Dm  1024
#define Hh  16
#define HD  64
#define MTOT (Bsz * Sq)   // 8192
#define NEL ((size_t)MTOT * Dm)   // 8M
#define WEL ((size_t)Dm * Dm)     // 1M

// Scratch (device globals — no allocation allowed). All tf32-bit uint32.
__device__ uint32_t g_qc[NEL];
__device__ uint32_t g_kc[NEL];
__device__ uint32_t g_vc[NEL];
__device__ uint32_t g_wc[4 * WEL];
__device__ uint32_t g_xq[NEL];
__device__ uint32_t g_xk[NEL];
__device__ uint32_t g_xv[NEL];
__device__ uint32_t g_ao[NEL];

// ===========================================================================
// Helpers
// ===========================================================================
__device__ __forceinline__ uint32_t smem_u32(const void* p) {
    uint32_t a;
    asm("{ .reg .u64 t; cvta.to.shared.u64 t, %1; cvt.u32.u64 %0, t; }"
        : "=r"(a) : "l"(p));
    return a;
}
__device__ __forceinline__ void cp16(uint32_t dst, const void* src) {
    asm volatile("cp.async.cg.shared.global [%0], [%1], 16;"
                 :: "r"(dst), "l"(src));
}
__device__ __forceinline__ void cp_commit() {
    asm volatile("cp.async.commit_group;" ::: "memory");
}
template<int N> __device__ __forceinline__ void cp_wait() {
    asm volatile("cp.async.wait_group %0;" :: "n"(N) : "memory");
}
__device__ __forceinline__ uint32_t f2tf32(float v) {
    uint32_t r;
    asm("cvt.rna.tf32.f32 %0, %1;" : "=r"(r) : "f"(v));
    return r;
}
__device__ __forceinline__ void mma_tf32(float* d, const uint32_t* a,
                                         const uint32_t* b) {
    asm volatile(
        "mma.sync.aligned.m16n8k8.row.col.f32.tf32.tf32.f32 "
        "{%0,%1,%2,%3}, {%4,%5,%6,%7}, {%8,%9}, {%0,%1,%2,%3};"
        : "+f"(d[0]), "+f"(d[1]), "+f"(d[2]), "+f"(d[3])
        : "r"(a[0]), "r"(a[1]), "r"(a[2]), "r"(a[3]),
          "r"(b[0]), "r"(b[1]));
}

// ===========================================================================
// Single fused pre-convert kernel: fp32 -> tf32 bits for all 7 tensors.
// ===========================================================================
#define I4 (NEL / 4)   // 2M float4 per input tensor
#define W4 (WEL / 4)   // 256K float4 per weight

__global__ __launch_bounds__(256) void conv_all(
    const float* __restrict__ q, const float* __restrict__ k,
    const float* __restrict__ v, const float* __restrict__ wq,
    const float* __restrict__ wk, const float* __restrict__ wv,
    const float* __restrict__ wo)
{
    size_t i = (size_t)blockIdx.x * 256 + threadIdx.x;
    const float* src;
    uint32_t* dst;
    size_t off;
    float sc = 1.f;
    if (i < I4)            { src = q; dst = g_qc; off = i; sc = 0.125f; }
    else if (i < 2 * I4)   { src = k; dst = g_kc; off = i - I4; }
    else if (i < 3 * I4)   { src = v; dst = g_vc; off = i - 2 * I4; }
    else {
        size_t j = i - 3 * I4;
        int w = (int)(j / W4);
        off = j % W4;
        src = (w == 0) ? wq : (w == 1) ? wk : (w == 2) ? wv : wo;
        dst = g_wc + (size_t)w * WEL;
    }
    float4 x = reinterpret_cast<const float4*>(src)[off];
    uint4 u;
    u.x = f2tf32(x.x * sc); u.y = f2tf32(x.y * sc);
    u.z = f2tf32(x.z * sc); u.w = f2tf32(x.w * sc);
    reinterpret_cast<uint4*>(dst)[off] = u;
}
#define CONV_BLOCKS ((int)((3 * I4 + 4 * W4 + 255) / 256))

// ===========================================================================
// Tensor-core GEMM on pre-converted tf32 operands (2 CTAs/SM).
// ===========================================================================
#define BK 32
#define NC (Dm / BK)
#define LDA 36
#define HALF_OFF (128 * LDA * 4)
#define STAGE_BYTES (2 * 128 * LDA * 4)   // 36864
#define GSMEM (2 * STAGE_BYTES)           // 73728

__device__ __forceinline__ void load_chunk(uint32_t sbase, int stage,
                                           const uint32_t* A, const uint32_t* W,
                                           int row0, int col0, int kb, int tid) {
    uint32_t a_st = sbase + stage * STAGE_BYTES;
    uint32_t w_st = a_st + HALF_OFF;
    #pragma unroll
    for (int p = 0; p < 4; p++) {
        int idx = tid + p * 256;
        int r  = idx >> 3;
        int cq = idx & 7;
        uint32_t d = (uint32_t)(r * (LDA * 4) + cq * 16);
        cp16(a_st + d, A + (size_t)(row0 + r) * Dm + kb + cq * 4);
        cp16(w_st + d, W + (size_t)(col0 + r) * Dm + kb + cq * 4);
    }
    cp_commit();
}

__global__ __launch_bounds__(256, 2) void gemm_tc(float* __restrict__ Cp,
                                                  int asel, int wsel, int csel)
{
    extern __shared__ char smem[];
    uint32_t sbase = smem_u32(smem);
    const uint32_t* A = (asel == 0) ? g_qc : (asel == 1) ? g_kc
                       : (asel == 2) ? g_vc : g_ao;
    const uint32_t* W = g_wc + (size_t)wsel * WEL;
    uint32_t* Cu = (csel == 1) ? g_xq : (csel == 2) ? g_xk : g_xv;

    const int tid = threadIdx.x;
    const int wid = tid >> 5;
    const int lid = tid & 31;
    const int g   = lid >> 2;
    const int tg  = lid & 3;
    const int wr  = wid >> 2;
    const int wc  = wid & 3;
    const int row0 = blockIdx.y * 128;
    const int col0 = blockIdx.x * 128;

    float acc[4][4][4];
    #pragma unroll
    for (int mt = 0; mt < 4; mt++)
        #pragma unroll
        for (int nt = 0; nt < 4; nt++)
            #pragma unroll
            for (int q = 0; q < 4; q++) acc[mt][nt][q] = 0.f;

    load_chunk(sbase, 0, A, W, row0, col0, 0, tid);

    for (int c = 0; c < NC; c++) {
        if (c + 1 < NC) {
            load_chunk(sbase, (c + 1) & 1, A, W, row0, col0, (c + 1) * BK, tid);
            cp_wait<1>();
        } else {
            cp_wait<0>();
        }
        __syncthreads();

        const uint32_t* As = (const uint32_t*)(smem + (c & 1) * STAGE_BYTES);
        const uint32_t* Ws = (const uint32_t*)(smem + (c & 1) * STAGE_BYTES + HALF_OFF);

        #pragma unroll
        for (int ks = 0; ks < 4; ks++) {
            const int k0 = ks * 8;
            uint32_t af[4][4], bf[4][2];
            #pragma unroll
            for (int mt = 0; mt < 4; mt++) {
                int row = wr * 64 + mt * 16;
                af[mt][0] = As[(row + g) * LDA + k0 + tg];
                af[mt][1] = As[(row + g + 8) * LDA + k0 + tg];
                af[mt][2] = As[(row + g) * LDA + k0 + tg + 4];
                af[mt][3] = As[(row + g + 8) * LDA + k0 + tg + 4];
            }
            #pragma unroll
            for (int nt = 0; nt < 4; nt++) {
                int col = wc * 32 + nt * 8;
                bf[nt][0] = Ws[(col + g) * LDA + k0 + tg];
                bf[nt][1] = Ws[(col + g) * LDA + k0 + tg + 4];
            }
            #pragma unroll
            for (int mt = 0; mt < 4; mt++)
                #pragma unroll
                for (int nt = 0; nt < 4; nt++)
                    mma_tf32(acc[mt][nt], af[mt], bf[nt]);
        }
        __syncthreads();
    }

    #pragma unroll
    for (int mt = 0; mt < 4; mt++) {
        int row = row0 + wr * 64 + mt * 16 + g;
        #pragma unroll
        for (int nt = 0; nt < 4; nt++) {
            int col = col0 + wc * 32 + nt * 8 + 2 * tg;
            if (csel == 0) {
                *reinterpret_cast<float2*>(&Cp[(size_t)row * Dm + col]) =
                    make_float2(acc[mt][nt][0], acc[mt][nt][1]);
                *reinterpret_cast<float2*>(&Cp[(size_t)(row + 8) * Dm + col]) =
                    make_float2(acc[mt][nt][2], acc[mt][nt][3]);
            } else {
                uint2 u0 = make_uint2(f2tf32(acc[mt][nt][0]), f2tf32(acc[mt][nt][1]));
                uint2 u1 = make_uint2(f2tf32(acc[mt][nt][2]), f2tf32(acc[mt][nt][3]));
                *reinterpret_cast<uint2*>(&Cu[(size_t)row * Dm + col]) = u0;
                *reinterpret_cast<uint2*>(&Cu[(size_t)(row + 8) * Dm + col]) = u1;
            }
        }
    }
}

// ===========================================================================
// Flash attention (causal), tf32 mma.sync.
// cp.async double-buffered K/V, V kept natural (no transpose, LDV=72).
// BQ=128 (8 warps x 16 rows), BKV=64, HD=64, 256 threads.
// ===========================================================================
#define LDK 68                         // K/P/Q row stride (banks 4g+tg: perfect)
#define LDV 72                         // V row stride (banks 8tg+g: perfect)
#define KS_BYTES (64 * LDK * 4)        // 17408 per stage
#define VS_BYTES (64 * LDV * 4)        // 18432 per stage
#define KS_OFF 0                       // [2][64*LDK]
#define VS_OFF (2 * KS_BYTES)          // [2][64*LDV]
#define PS_OFF (VS_OFF + 2 * VS_BYTES) // [128*LDK]
#define AT_SMEM (PS_OFF + 128 * LDK * 4)   // 106496 bytes

__device__ __forceinline__ void load_kv(uint32_t sbase, int stage,
                                        const uint32_t* Kp, const uint32_t* Vp,
                                        int jt, int tid) {
    uint32_t k_st = sbase + KS_OFF + stage * KS_BYTES;
    uint32_t v_st = sbase + VS_OFF + stage * VS_BYTES;
    #pragma unroll
    for (int p = 0; p < 4; p++) {
        int idx = tid + p * 256;       // 0..1023
        int r   = idx >> 4;            // 0..63
        int c4  = idx & 15;
        size_t goff = (size_t)(jt * 64 + r) * Dm + c4 * 4;
        cp16(k_st + (uint32_t)(r * LDK + c4 * 4) * 4, Kp + goff);
        cp16(v_st + (uint32_t)(r * LDV + c4 * 4) * 4, Vp + goff);
    }
    cp_commit();
}

__global__ __launch_bounds__(256) void flash_attn_tc()
{
    extern __shared__ char smem[];
    uint32_t sbase = smem_u32(smem);
    uint32_t* KsB = (uint32_t*)(smem + KS_OFF);
    uint32_t* VsB = (uint32_t*)(smem + VS_OFF);
    uint32_t* Ps  = (uint32_t*)(smem + PS_OFF);

    const int qt = (gridDim.x - 1) - blockIdx.x;   // heavy tiles first
    const int bh = blockIdx.y;
    const int b  = bh >> 4;
    const int h  = bh & 15;
    const int q0 = qt * 128;

    const size_t base = (size_t)b * Sq * Dm + (size_t)h * HD;
    const uint32_t* Qp = g_xq + base;
    const uint32_t* Kp = g_xk + base;
    const uint32_t* Vp = g_xv + base;
    uint32_t*       Op = g_ao + base;

    const int tid = threadIdx.x;
    const int wid = tid >> 5;
    const int lid = tid & 31;
    const int g   = lid >> 2;
    const int tg  = lid & 3;
    const int wrow = wid * 16;
    const int ntl = 2 * qt + 2;

    // ---- Prologue: stage Q (group 0) and KV tile 0 (group 1) --------------
    {
        uint32_t p_st = sbase + PS_OFF;
        #pragma unroll
        for (int p = 0; p < 8; p++) {
            int idx = tid + p * 256;
            int r   = idx >> 4;
            int c4  = idx & 15;
            cp16(p_st + (uint32_t)(r * LDK + c4 * 4) * 4,
                 Qp + (size_t)(q0 + r) * Dm + c4 * 4);
        }
        cp_commit();
    }
    load_kv(sbase, 0, Kp, Vp, 0, tid);
    cp_wait<1>();          // Q resident
    __syncthreads();

    uint32_t qf[8][4];
    #pragma unroll
    for (int kt = 0; kt < 8; kt++) {
        int k0 = kt * 8;
        qf[kt][0] = Ps[(wrow + g) * LDK + k0 + tg];
        qf[kt][1] = Ps[(wrow + g + 8) * LDK + k0 + tg];
        qf[kt][2] = Ps[(wrow + g) * LDK + k0 + tg + 4];
        qf[kt][3] = Ps[(wrow + g + 8) * LDK + k0 + tg + 4];
    }

    float m0 = -1e30f, m1 = -1e30f, l0 = 0.f, l1 = 0.f;
    float o[8][4];
    #pragma unroll
    for (int nt = 0; nt < 8; nt++)
        #pragma unroll
        for (int q = 0; q < 4; q++) o[nt][q] = 0.f;

    const int row_g  = q0 + wrow + g;
    const int row_g8 = row_g + 8;

    for (int jt = 0; jt < ntl; jt++) {
        const int s = jt & 1;
        if (jt + 1 < ntl) {
            load_kv(sbase, s ^ 1, Kp, Vp, jt + 1, tid);   // prefetch
            cp_wait<1>();                                  // tile jt resident
        } else {
            cp_wait<0>();
        }
        __syncthreads();

        if (jt * 64 <= q0 + wrow + 15) {
            const uint32_t* Ks = KsB + s * (64 * LDK);
            const uint32_t* Vs = VsB + s * (64 * LDV);

            // ---- S = Q K^T ----
            float sacc[8][4];
            #pragma unroll
            for (int nt = 0; nt < 8; nt++)
                #pragma unroll
                for (int q = 0; q < 4; q++) sacc[nt][q] = 0.f;

            #pragma unroll
            for (int nt = 0; nt < 8; nt++) {
                #pragma unroll
                for (int kt = 0; kt < 8; kt++) {
                    int k0 = kt * 8;
                    uint32_t bf[2];
                    bf[0] = Ks[(nt * 8 + g) * LDK + k0 + tg];
                    bf[1] = Ks[(nt * 8 + g) * LDK + k0 + tg + 4];
                    mma_tf32(sacc[nt], qf[kt], bf);
                }
            }

            // ---- Causal mask (diagonal tiles only) ----
            if (jt >= 2 * qt) {
                #pragma unroll
                for (int nt = 0; nt < 8; nt++) {
                    int cb = jt * 64 + nt * 8 + 2 * tg;
                    if (cb     > row_g ) sacc[nt][0] = -1e30f;
                    if (cb + 1 > row_g ) sacc[nt][1] = -1e30f;
                    if (cb     > row_g8) sacc[nt][2] = -1e30f;
                    if (cb + 1 > row_g8) sacc[nt][3] = -1e30f;
                }
            }

            // ---- Online softmax ----
            float mn0 = m0, mn1 = m1;
            #pragma unroll
            for (int nt = 0; nt < 8; nt++) {
                mn0 = fmaxf(mn0, fmaxf(sacc[nt][0], sacc[nt][1]));
                mn1 = fmaxf(mn1, fmaxf(sacc[nt][2], sacc[nt][3]));
            }
            mn0 = fmaxf(mn0, __shfl_xor_sync(0xffffffffu, mn0, 1));
            mn0 = fmaxf(mn0, __shfl_xor_sync(0xffffffffu, mn0, 2));
            mn1 = fmaxf(mn1, __shfl_xor_sync(0xffffffffu, mn1, 1));
            mn1 = fmaxf(mn1, __shfl_xor_sync(0xffffffffu, mn1, 2));

            float sc0 = __expf(m0 - mn0);
            float sc1 = __expf(m1 - mn1);
            m0 = mn0; m1 = mn1;

            float ls0 = 0.f, ls1 = 0.f;
            #pragma unroll
            for (int nt = 0; nt < 8; nt++) {
                float p0 = __expf(sacc[nt][0] - mn0);
                float p1 = __expf(sacc[nt][1] - mn0);
                float p2 = __expf(sacc[nt][2] - mn1);
                float p3 = __expf(sacc[nt][3] - mn1);
                ls0 += p0 + p1;
                ls1 += p2 + p3;
                int col = nt * 8 + 2 * tg;
                *reinterpret_cast<uint2*>(&Ps[(wrow + g) * LDK + col]) =
                    make_uint2(f2tf32(p0), f2tf32(p1));
                *reinterpret_cast<uint2*>(&Ps[(wrow + g + 8) * LDK + col]) =
                    make_uint2(f2tf32(p2), f2tf32(p3));
            }
            ls0 += __shfl_xor_sync(0xffffffffu, ls0, 1);
            ls0 += __shfl_xor_sync(0xffffffffu, ls0, 2);
            ls1 += __shfl_xor_sync(0xffffffffu, ls1, 1);
            ls1 += __shfl_xor_sync(0xffffffffu, ls1, 2);
            l0 = l0 * sc0 + ls0;
            l1 = l1 * sc1 + ls1;

            #pragma unroll
            for (int nt = 0; nt < 8; nt++) {
                o[nt][0] *= sc0; o[nt][1] *= sc0;
                o[nt][2] *= sc1; o[nt][3] *= sc1;
            }
            __syncwarp();

            // ---- O += P V  (V natural layout, B-frag rows k0+tg / k0+tg+4)
            #pragma unroll
            for (int kt = 0; kt < 8; kt++) {
                int k0 = kt * 8;
                uint32_t ap[4];
                ap[0] = Ps[(wrow + g) * LDK + k0 + tg];
                ap[1] = Ps[(wrow + g + 8) * LDK + k0 + tg];
                ap[2] = Ps[(wrow + g) * LDK + k0 + tg + 4];
                ap[3] = Ps[(wrow + g + 8) * LDK + k0 + tg + 4];
                #pragma unroll
                for (int nt = 0; nt < 8; nt++) {
                    uint32_t bf[2];
                    bf[0] = Vs[(k0 + tg) * LDV + nt * 8 + g];
                    bf[1] = Vs[(k0 + tg + 4) * LDV + nt * 8 + g];
                    mma_tf32(o[nt], ap, bf);
                }
            }
        }
        __syncthreads();   // stage s free for the prefetch issued next iter
    }

    // ---- Epilogue ----
    float il0 = 1.f / l0, il1 = 1.f / l1;
    #pragma unroll
    for (int nt = 0; nt < 8; nt++) {
        int col = nt * 8 + 2 * tg;
        *reinterpret_cast<uint2*>(&Op[(size_t)(row_g) * Dm + col]) =
            make_uint2(f2tf32(o[nt][0] * il0), f2tf32(o[nt][1] * il0));
        *reinterpret_cast<uint2*>(&Op[(size_t)(row_g8) * Dm + col]) =
            make_uint2(f2tf32(o[nt][2] * il1), f2tf32(o[nt][3] * il1));
    }
}

// ---------------------------------------------------------------------------
// Launch
// ---------------------------------------------------------------------------
extern "C" void kernel_launch(void* const* d_in, const int* in_sizes, int n_in,
                              void* d_out, int out_size)
{
    const float* q  = (const float*)d_in[0];
    const float* k  = (const float*)d_in[1];
    const float* v  = (const float*)d_in[2];
    const float* wq = (const float*)d_in[3];
    const float* wk = (const float*)d_in[4];
    const float* wv = (const float*)d_in[5];
    const float* wo = (const float*)d_in[6];
    float* out = (float*)d_out;

    cudaFuncSetAttribute(gemm_tc, cudaFuncAttributeMaxDynamicSharedMemorySize,
                         GSMEM);
    cudaFuncSetAttribute(flash_attn_tc,
                         cudaFuncAttributeMaxDynamicSharedMemorySize, AT_SMEM);

    conv_all<<<CONV_BLOCKS, 256>>>(q, k, v, wq, wk, wv, wo);

    dim3 ggrid(Dm / 128, MTOT / 128, 1);   // (8, 64)
    gemm_tc<<<ggrid, 256, GSMEM>>>(nullptr, 0, 0, 1);   // Q proj
    gemm_tc<<<ggrid, 256, GSMEM>>>(nullptr, 1, 1, 2);   // K proj
    gemm_tc<<<ggrid, 256, GSMEM>>>(nullptr, 2, 2, 3);   // V proj

    dim3 agrid(Sq / 128, Bsz * Hh, 1);     // (16, 64)
    flash_attn_tc<<<agrid, 256, AT_SMEM>>>();

    gemm_tc<<<ggrid, 256, GSMEM>>>(out, 3, 3, 0);       // O proj -> fp32 out
}

// round 8
// speedup vs baseline: 4.5062x; 1.0259x over previous
#include <cuda_runtime.h>
#include <cstdint>
#include <math.h>

// Problem constants
#define Bsz 4
#define Sq  2048
#define Dm  1024
#define Hh  16
#define HD  64
#define MTOT (Bsz * Sq)   // 8192
#define NEL ((size_t)MTOT * Dm)   // 8M
#define WEL ((size_t)Dm * Dm)     // 1M

// Scratch (device globals — no allocation allowed). All tf32-bit uint32.
__device__ uint32_t g_qc[NEL];
__device__ uint32_t g_kc[NEL];
__device__ uint32_t g_vc[NEL];
__device__ uint32_t g_wc[4 * WEL];
__device__ uint32_t g_xq[NEL];
__device__ uint32_t g_xk[NEL];
__device__ uint32_t g_xv[NEL];
__device__ uint32_t g_ao[NEL];

// ===========================================================================
// Helpers
// ===========================================================================
__device__ __forceinline__ uint32_t smem_u32(const void* p) {
    uint32_t a;
    asm("{ .reg .u64 t; cvta.to.shared.u64 t, %1; cvt.u32.u64 %0, t; }"
        : "=r"(a) : "l"(p));
    return a;
}
__device__ __forceinline__ void cp16(uint32_t dst, const void* src) {
    asm volatile("cp.async.cg.shared.global [%0], [%1], 16;"
                 :: "r"(dst), "l"(src));
}
__device__ __forceinline__ void cp_commit() {
    asm volatile("cp.async.commit_group;" ::: "memory");
}
template<int N> __device__ __forceinline__ void cp_wait() {
    asm volatile("cp.async.wait_group %0;" :: "n"(N) : "memory");
}
__device__ __forceinline__ uint32_t f2tf32(float v) {
    uint32_t r;
    asm("cvt.rna.tf32.f32 %0, %1;" : "=r"(r) : "f"(v));
    return r;
}
__device__ __forceinline__ void mma_tf32(float* d, const uint32_t* a,
                                         const uint32_t* b) {
    asm volatile(
        "mma.sync.aligned.m16n8k8.row.col.f32.tf32.tf32.f32 "
        "{%0,%1,%2,%3}, {%4,%5,%6,%7}, {%8,%9}, {%0,%1,%2,%3};"
        : "+f"(d[0]), "+f"(d[1]), "+f"(d[2]), "+f"(d[3])
        : "r"(a[0]), "r"(a[1]), "r"(a[2]), "r"(a[3]),
          "r"(b[0]), "r"(b[1]));
}

// ===========================================================================
// Single fused pre-convert kernel: fp32 -> tf32 bits for all 7 tensors.
// ===========================================================================
#define I4 (NEL / 4)
#define W4 (WEL / 4)

__global__ __launch_bounds__(256) void conv_all(
    const float* __restrict__ q, const float* __restrict__ k,
    const float* __restrict__ v, const float* __restrict__ wq,
    const float* __restrict__ wk, const float* __restrict__ wv,
    const float* __restrict__ wo)
{
    size_t i = (size_t)blockIdx.x * 256 + threadIdx.x;
    const float* src;
    uint32_t* dst;
    size_t off;
    float sc = 1.f;
    if (i < I4)            { src = q; dst = g_qc; off = i; sc = 0.125f; }
    else if (i < 2 * I4)   { src = k; dst = g_kc; off = i - I4; }
    else if (i < 3 * I4)   { src = v; dst = g_vc; off = i - 2 * I4; }
    else {
        size_t j = i - 3 * I4;
        int w = (int)(j / W4);
        off = j % W4;
        src = (w == 0) ? wq : (w == 1) ? wk : (w == 2) ? wv : wo;
        dst = g_wc + (size_t)w * WEL;
    }
    float4 x = reinterpret_cast<const float4*>(src)[off];
    uint4 u;
    u.x = f2tf32(x.x * sc); u.y = f2tf32(x.y * sc);
    u.z = f2tf32(x.z * sc); u.w = f2tf32(x.w * sc);
    reinterpret_cast<uint4*>(dst)[off] = u;
}
#define CONV_BLOCKS ((int)((3 * I4 + 4 * W4 + 255) / 256))

// ===========================================================================
// Tensor-core GEMM on pre-converted tf32 operands (2 CTAs/SM).
// asel=-1: fused QKV mode — blockIdx.z selects projection 0/1/2.
// ===========================================================================
#define BK 32
#define NC (Dm / BK)
#define LDA 36
#define HALF_OFF (128 * LDA * 4)
#define STAGE_BYTES (2 * 128 * LDA * 4)   // 36864
#define GSMEM (2 * STAGE_BYTES)           // 73728

__device__ __forceinline__ void load_chunk(uint32_t sbase, int stage,
                                           const uint32_t* A, const uint32_t* W,
                                           int row0, int col0, int kb, int tid) {
    uint32_t a_st = sbase + stage * STAGE_BYTES;
    uint32_t w_st = a_st + HALF_OFF;
    #pragma unroll
    for (int p = 0; p < 4; p++) {
        int idx = tid + p * 256;
        int r  = idx >> 3;
        int cq = idx & 7;
        uint32_t d = (uint32_t)(r * (LDA * 4) + cq * 16);
        cp16(a_st + d, A + (size_t)(row0 + r) * Dm + kb + cq * 4);
        cp16(w_st + d, W + (size_t)(col0 + r) * Dm + kb + cq * 4);
    }
    cp_commit();
}

__global__ __launch_bounds__(256, 2) void gemm_tc(float* __restrict__ Cp,
                                                  int asel, int wsel, int csel)
{
    extern __shared__ char smem[];
    uint32_t sbase = smem_u32(smem);
    const int az = (asel < 0) ? (int)blockIdx.z : asel;
    const int wz = (asel < 0) ? (int)blockIdx.z : wsel;
    const int cz = (asel < 0) ? (int)blockIdx.z + 1 : csel;

    const uint32_t* A = (az == 0) ? g_qc : (az == 1) ? g_kc
                       : (az == 2) ? g_vc : g_ao;
    const uint32_t* W = g_wc + (size_t)wz * WEL;
    uint32_t* Cu = (cz == 1) ? g_xq : (cz == 2) ? g_xk : g_xv;

    const int tid = threadIdx.x;
    const int wid = tid >> 5;
    const int lid = tid & 31;
    const int g   = lid >> 2;
    const int tg  = lid & 3;
    const int wr  = wid >> 2;
    const int wc  = wid & 3;
    const int row0 = blockIdx.y * 128;
    const int col0 = blockIdx.x * 128;

    float acc[4][4][4];
    #pragma unroll
    for (int mt = 0; mt < 4; mt++)
        #pragma unroll
        for (int nt = 0; nt < 4; nt++)
            #pragma unroll
            for (int q = 0; q < 4; q++) acc[mt][nt][q] = 0.f;

    load_chunk(sbase, 0, A, W, row0, col0, 0, tid);

    for (int c = 0; c < NC; c++) {
        if (c + 1 < NC) {
            load_chunk(sbase, (c + 1) & 1, A, W, row0, col0, (c + 1) * BK, tid);
            cp_wait<1>();
        } else {
            cp_wait<0>();
        }
        __syncthreads();

        const uint32_t* As = (const uint32_t*)(smem + (c & 1) * STAGE_BYTES);
        const uint32_t* Ws = (const uint32_t*)(smem + (c & 1) * STAGE_BYTES + HALF_OFF);

        #pragma unroll
        for (int ks = 0; ks < 4; ks++) {
            const int k0 = ks * 8;
            uint32_t af[4][4], bf[4][2];
            #pragma unroll
            for (int mt = 0; mt < 4; mt++) {
                int row = wr * 64 + mt * 16;
                af[mt][0] = As[(row + g) * LDA + k0 + tg];
                af[mt][1] = As[(row + g + 8) * LDA + k0 + tg];
                af[mt][2] = As[(row + g) * LDA + k0 + tg + 4];
                af[mt][3] = As[(row + g + 8) * LDA + k0 + tg + 4];
            }
            #pragma unroll
            for (int nt = 0; nt < 4; nt++) {
                int col = wc * 32 + nt * 8;
                bf[nt][0] = Ws[(col + g) * LDA + k0 + tg];
                bf[nt][1] = Ws[(col + g) * LDA + k0 + tg + 4];
            }
            #pragma unroll
            for (int mt = 0; mt < 4; mt++)
                #pragma unroll
                for (int nt = 0; nt < 4; nt++)
                    mma_tf32(acc[mt][nt], af[mt], bf[nt]);
        }
        __syncthreads();
    }

    #pragma unroll
    for (int mt = 0; mt < 4; mt++) {
        int row = row0 + wr * 64 + mt * 16 + g;
        #pragma unroll
        for (int nt = 0; nt < 4; nt++) {
            int col = col0 + wc * 32 + nt * 8 + 2 * tg;
            if (cz == 0) {
                *reinterpret_cast<float2*>(&Cp[(size_t)row * Dm + col]) =
                    make_float2(acc[mt][nt][0], acc[mt][nt][1]);
                *reinterpret_cast<float2*>(&Cp[(size_t)(row + 8) * Dm + col]) =
                    make_float2(acc[mt][nt][2], acc[mt][nt][3]);
            } else {
                uint2 u0 = make_uint2(f2tf32(acc[mt][nt][0]), f2tf32(acc[mt][nt][1]));
                uint2 u1 = make_uint2(f2tf32(acc[mt][nt][2]), f2tf32(acc[mt][nt][3]));
                *reinterpret_cast<uint2*>(&Cu[(size_t)row * Dm + col]) = u0;
                *reinterpret_cast<uint2*>(&Cu[(size_t)(row + 8) * Dm + col]) = u1;
            }
        }
    }
}

// ===========================================================================
// Flash attention (causal), tf32 mma.sync, 2 CTAs/SM.
// Persistent Q SMEM + separate P SMEM; KV single-buffered cp.async.
// BQ=128 (8 warps x 16 rows), BKV=64, HD=64, 256 threads.
// ===========================================================================
#define LDK 68                        // Q/K/P stride (banks 4g+tg: perfect)
#define LDV 72                        // V stride (banks 8tg+g: perfect)
#define QS_OFF 0                      // [128*LDK] 34816 B
#define PS_OFF (128 * LDK * 4)        // [128*LDK] 34816 B
#define KS_OFF (PS_OFF + 128 * LDK * 4)        // [64*LDK] 17408 B
#define VS_OFF (KS_OFF + 64 * LDK * 4)         // [64*LDV] 18432 B
#define AT_SMEM (VS_OFF + 64 * LDV * 4)        // 105472 B -> 2 CTAs/SM

__device__ __forceinline__ void load_kv(uint32_t sbase,
                                        const uint32_t* Kp, const uint32_t* Vp,
                                        int jt, int tid) {
    uint32_t k_st = sbase + KS_OFF;
    uint32_t v_st = sbase + VS_OFF;
    #pragma unroll
    for (int p = 0; p < 4; p++) {
        int idx = tid + p * 256;       // 0..1023
        int r   = idx >> 4;            // 0..63
        int c4  = idx & 15;
        size_t goff = (size_t)(jt * 64 + r) * Dm + c4 * 4;
        cp16(k_st + (uint32_t)(r * LDK + c4 * 4) * 4, Kp + goff);
        cp16(v_st + (uint32_t)(r * LDV + c4 * 4) * 4, Vp + goff);
    }
    cp_commit();
}

__global__ __launch_bounds__(256, 2) void flash_attn_tc()
{
    extern __shared__ char smem[];
    uint32_t sbase = smem_u32(smem);
    const uint32_t* Qs = (const uint32_t*)(smem + QS_OFF);
    uint32_t*       Ps = (uint32_t*)(smem + PS_OFF);
    const uint32_t* Ks = (const uint32_t*)(smem + KS_OFF);
    const uint32_t* Vs = (const uint32_t*)(smem + VS_OFF);

    const int qt = (gridDim.x - 1) - blockIdx.x;   // heavy tiles first
    const int bh = blockIdx.y;
    const int b  = bh >> 4;
    const int h  = bh & 15;
    const int q0 = qt * 128;

    const size_t base = (size_t)b * Sq * Dm + (size_t)h * HD;
    const uint32_t* Qp = g_xq + base;
    const uint32_t* Kp = g_xk + base;
    const uint32_t* Vp = g_xv + base;
    uint32_t*       Op = g_ao + base;

    const int tid = threadIdx.x;
    const int wid = tid >> 5;
    const int lid = tid & 31;
    const int g   = lid >> 2;
    const int tg  = lid & 3;
    const int wrow = wid * 16;
    const int ntl = 2 * qt + 2;

    // ---- Prologue: stage Q and KV tile 0 ----------------------------------
    {
        uint32_t q_st = sbase + QS_OFF;
        #pragma unroll
        for (int p = 0; p < 8; p++) {
            int idx = tid + p * 256;
            int r   = idx >> 4;
            int c4  = idx & 15;
            cp16(q_st + (uint32_t)(r * LDK + c4 * 4) * 4,
                 Qp + (size_t)(q0 + r) * Dm + c4 * 4);
        }
        cp_commit();
    }
    load_kv(sbase, Kp, Vp, 0, tid);
    cp_wait<0>();
    __syncthreads();

    float m0 = -1e30f, m1 = -1e30f, l0 = 0.f, l1 = 0.f;
    float o[8][4];
    #pragma unroll
    for (int nt = 0; nt < 8; nt++)
        #pragma unroll
        for (int q = 0; q < 4; q++) o[nt][q] = 0.f;

    const int row_g  = q0 + wrow + g;
    const int row_g8 = row_g + 8;

    for (int jt = 0; jt < ntl; jt++) {
        if (jt * 64 <= q0 + wrow + 15) {
            // ---- S = Q K^T (Q fragments re-read from persistent Qs) ----
            float sacc[8][4];
            #pragma unroll
            for (int nt = 0; nt < 8; nt++)
                #pragma unroll
                for (int q = 0; q < 4; q++) sacc[nt][q] = 0.f;

            #pragma unroll
            for (int kt = 0; kt < 8; kt++) {
                int k0 = kt * 8;
                uint32_t af[4];
                af[0] = Qs[(wrow + g) * LDK + k0 + tg];
                af[1] = Qs[(wrow + g + 8) * LDK + k0 + tg];
                af[2] = Qs[(wrow + g) * LDK + k0 + tg + 4];
                af[3] = Qs[(wrow + g + 8) * LDK + k0 + tg + 4];
                #pragma unroll
                for (int nt = 0; nt < 8; nt++) {
                    uint32_t bf[2];
                    bf[0] = Ks[(nt * 8 + g) * LDK + k0 + tg];
                    bf[1] = Ks[(nt * 8 + g) * LDK + k0 + tg + 4];
                    mma_tf32(sacc[nt], af, bf);
                }
            }

            // ---- Causal mask (diagonal tiles only) ----
            if (jt >= 2 * qt) {
                #pragma unroll
                for (int nt = 0; nt < 8; nt++) {
                    int cb = jt * 64 + nt * 8 + 2 * tg;
                    if (cb     > row_g ) sacc[nt][0] = -1e30f;
                    if (cb + 1 > row_g ) sacc[nt][1] = -1e30f;
                    if (cb     > row_g8) sacc[nt][2] = -1e30f;
                    if (cb + 1 > row_g8) sacc[nt][3] = -1e30f;
                }
            }

            // ---- Online softmax ----
            float mn0 = m0, mn1 = m1;
            #pragma unroll
            for (int nt = 0; nt < 8; nt++) {
                mn0 = fmaxf(mn0, fmaxf(sacc[nt][0], sacc[nt][1]));
                mn1 = fmaxf(mn1, fmaxf(sacc[nt][2], sacc[nt][3]));
            }
            mn0 = fmaxf(mn0, __shfl_xor_sync(0xffffffffu, mn0, 1));
            mn0 = fmaxf(mn0, __shfl_xor_sync(0xffffffffu, mn0, 2));
            mn1 = fmaxf(mn1, __shfl_xor_sync(0xffffffffu, mn1, 1));
            mn1 = fmaxf(mn1, __shfl_xor_sync(0xffffffffu, mn1, 2));

            float sc0 = __expf(m0 - mn0);
            float sc1 = __expf(m1 - mn1);
            m0 = mn0; m1 = mn1;

            float ls0 = 0.f, ls1 = 0.f;
            #pragma unroll
            for (int nt = 0; nt < 8; nt++) {
                float p0 = __expf(sacc[nt][0] - mn0);
                float p1 = __expf(sacc[nt][1] - mn0);
                float p2 = __expf(sacc[nt][2] - mn1);
                float p3 = __expf(sacc[nt][3] - mn1);
                ls0 += p0 + p1;
                ls1 += p2 + p3;
                int col = nt * 8 + 2 * tg;
                *reinterpret_cast<uint2*>(&Ps[(wrow + g) * LDK + col]) =
                    make_uint2(f2tf32(p0), f2tf32(p1));
                *reinterpret_cast<uint2*>(&Ps[(wrow + g + 8) * LDK + col]) =
                    make_uint2(f2tf32(p2), f2tf32(p3));
            }
            ls0 += __shfl_xor_sync(0xffffffffu, ls0, 1);
            ls0 += __shfl_xor_sync(0xffffffffu, ls0, 2);
            ls1 += __shfl_xor_sync(0xffffffffu, ls1, 1);
            ls1 += __shfl_xor_sync(0xffffffffu, ls1, 2);
            l0 = l0 * sc0 + ls0;
            l1 = l1 * sc1 + ls1;

            #pragma unroll
            for (int nt = 0; nt < 8; nt++) {
                o[nt][0] *= sc0; o[nt][1] *= sc0;
                o[nt][2] *= sc1; o[nt][3] *= sc1;
            }
            __syncwarp();

            // ---- O += P V ----
            #pragma unroll
            for (int kt = 0; kt < 8; kt++) {
                int k0 = kt * 8;
                uint32_t ap[4];
                ap[0] = Ps[(wrow + g) * LDK + k0 + tg];
                ap[1] = Ps[(wrow + g + 8) * LDK + k0 + tg];
                ap[2] = Ps[(wrow + g) * LDK + k0 + tg + 4];
                ap[3] = Ps[(wrow + g + 8) * LDK + k0 + tg + 4];
                #pragma unroll
                for (int nt = 0; nt < 8; nt++) {
                    uint32_t bf[2];
                    bf[0] = Vs[(k0 + tg) * LDV + nt * 8 + g];
                    bf[1] = Vs[(k0 + tg + 4) * LDV + nt * 8 + g];
                    mma_tf32(o[nt], ap, bf);
                }
            }
        }

        // ---- Single-buffer KV rotate -------------------------------------
        __syncthreads();                       // everyone done with Ks/Vs
        if (jt + 1 < ntl) {
            load_kv(sbase, Kp, Vp, jt + 1, tid);
            cp_wait<0>();
            __syncthreads();                   // KV(jt+1) visible to all
        }
    }

    // ---- Epilogue ----
    float il0 = 1.f / l0, il1 = 1.f / l1;
    #pragma unroll
    for (int nt = 0; nt < 8; nt++) {
        int col = nt * 8 + 2 * tg;
        *reinterpret_cast<uint2*>(&Op[(size_t)(row_g) * Dm + col]) =
            make_uint2(f2tf32(o[nt][0] * il0), f2tf32(o[nt][1] * il0));
        *reinterpret_cast<uint2*>(&Op[(size_t)(row_g8) * Dm + col]) =
            make_uint2(f2tf32(o[nt][2] * il1), f2tf32(o[nt][3] * il1));
    }
}

// ---------------------------------------------------------------------------
// Launch
// ---------------------------------------------------------------------------
extern "C" void kernel_launch(void* const* d_in, const int* in_sizes, int n_in,
                              void* d_out, int out_size)
{
    const float* q  = (const float*)d_in[0];
    const float* k  = (const float*)d_in[1];
    const float* v  = (const float*)d_in[2];
    const float* wq = (const float*)d_in[3];
    const float* wk = (const float*)d_in[4];
    const float* wv = (const float*)d_in[5];
    const float* wo = (const float*)d_in[6];
    float* out = (float*)d_out;

    cudaFuncSetAttribute(gemm_tc, cudaFuncAttributeMaxDynamicSharedMemorySize,
                         GSMEM);
    cudaFuncSetAttribute(flash_attn_tc,
                         cudaFuncAttributeMaxDynamicSharedMemorySize, AT_SMEM);

    conv_all<<<CONV_BLOCKS, 256>>>(q, k, v, wq, wk, wv, wo);

    dim3 gqkv(Dm / 128, MTOT / 128, 3);    // fused Q/K/V projections
    gemm_tc<<<gqkv, 256, GSMEM>>>(nullptr, -1, 0, 0);

    dim3 agrid(Sq / 128, Bsz * Hh, 1);     // (16, 64)
    flash_attn_tc<<<agrid, 256, AT_SMEM>>>();

    dim3 ggrid(Dm / 128, MTOT / 128, 1);   // O projection
    gemm_tc<<<ggrid, 256, GSMEM>>>(out, 3, 3, 0);
}

// round 9
// speedup vs baseline: 8.3813x; 1.8599x over previous
#include <cuda_runtime.h>
#include <cuda_fp16.h>
#include <cstdint>
#include <math.h>

// Problem constants
#define Bsz 4
#define Sq  2048
#define Dm  1024
#define Hh  16
#define HD  64
#define MTOT (Bsz * Sq)   // 8192
#define NEL ((size_t)MTOT * Dm)   // 8M
#define WEL ((size_t)Dm * Dm)     // 1M

// Scratch (device globals — no allocation allowed). All fp16.
__device__ __half g_qc[NEL];        // fp16(0.125 * q)
__device__ __half g_kc[NEL];
__device__ __half g_vc[NEL];
__device__ __half g_wc[4 * WEL];
__device__ __half g_xq[NEL];
__device__ __half g_xk[NEL];
__device__ __half g_xv[NEL];
__device__ __half g_ao[NEL];

// ===========================================================================
// Helpers
// ===========================================================================
__device__ __forceinline__ uint32_t smem_u32(const void* p) {
    uint32_t a;
    asm("{ .reg .u64 t; cvta.to.shared.u64 t, %1; cvt.u32.u64 %0, t; }"
        : "=r"(a) : "l"(p));
    return a;
}
__device__ __forceinline__ void cp16(uint32_t dst, const void* src) {
    asm volatile("cp.async.cg.shared.global [%0], [%1], 16;"
                 :: "r"(dst), "l"(src));
}
__device__ __forceinline__ void cp_commit() {
    asm volatile("cp.async.commit_group;" ::: "memory");
}
template<int N> __device__ __forceinline__ void cp_wait() {
    asm volatile("cp.async.wait_group %0;" :: "n"(N) : "memory");
}
__device__ __forceinline__ uint32_t pack_h2(float a, float b) {
    __half2 h = __floats2half2_rn(a, b);
    return *reinterpret_cast<uint32_t*>(&h);
}
__device__ __forceinline__ void ldsm4(uint32_t* r, uint32_t a) {
    asm volatile("ldmatrix.sync.aligned.m8n8.x4.shared.b16 {%0,%1,%2,%3}, [%4];"
        : "=r"(r[0]), "=r"(r[1]), "=r"(r[2]), "=r"(r[3]) : "r"(a));
}
__device__ __forceinline__ void ldsm4t(uint32_t* r, uint32_t a) {
    asm volatile("ldmatrix.sync.aligned.m8n8.x4.trans.shared.b16 {%0,%1,%2,%3}, [%4];"
        : "=r"(r[0]), "=r"(r[1]), "=r"(r[2]), "=r"(r[3]) : "r"(a));
}
// D(16x8) += A(16x16) * B(16x8), fp16 in, fp32 accumulate
__device__ __forceinline__ void mma_f16(float* d, const uint32_t* a,
                                        uint32_t b0, uint32_t b1) {
    asm volatile(
        "mma.sync.aligned.m16n8k16.row.col.f32.f16.f16.f32 "
        "{%0,%1,%2,%3}, {%4,%5,%6,%7}, {%8,%9}, {%0,%1,%2,%3};"
        : "+f"(d[0]), "+f"(d[1]), "+f"(d[2]), "+f"(d[3])
        : "r"(a[0]), "r"(a[1]), "r"(a[2]), "r"(a[3]), "r"(b0), "r"(b1));
}

// Shared lane offset for all ldmatrix patterns (in halves):
// sub = lid>>3, r = lid&7 ->  ((sub&1)*8 + r) * LDH + (sub>>1)*8
#define LDH 72

// ===========================================================================
// Fused pre-convert: fp32 -> fp16 for all 7 tensors (float4 granularity).
// ===========================================================================
#define I4 (NEL / 4)
#define W4 (WEL / 4)

__global__ __launch_bounds__(256) void conv_all(
    const float* __restrict__ q, const float* __restrict__ k,
    const float* __restrict__ v, const float* __restrict__ wq,
    const float* __restrict__ wk, const float* __restrict__ wv,
    const float* __restrict__ wo)
{
    size_t i = (size_t)blockIdx.x * 256 + threadIdx.x;
    const float* src;
    __half* dst;
    size_t off;
    float sc = 1.f;
    if (i < I4)            { src = q; dst = g_qc; off = i; sc = 0.125f; }
    else if (i < 2 * I4)   { src = k; dst = g_kc; off = i - I4; }
    else if (i < 3 * I4)   { src = v; dst = g_vc; off = i - 2 * I4; }
    else {
        size_t j = i - 3 * I4;
        int w = (int)(j / W4);
        off = j % W4;
        src = (w == 0) ? wq : (w == 1) ? wk : (w == 2) ? wv : wo;
        dst = g_wc + (size_t)w * WEL;
    }
    float4 x = reinterpret_cast<const float4*>(src)[off];
    uint2 u = make_uint2(pack_h2(x.x * sc, x.y * sc),
                         pack_h2(x.z * sc, x.w * sc));
    reinterpret_cast<uint2*>(dst)[off] = u;
}
#define CONV_BLOCKS ((int)((3 * I4 + 4 * W4 + 255) / 256))

// ===========================================================================
// fp16 tensor-core GEMM: C[m,n] = sum_k A[m,k]*W[n,k]  (M=8192, N=K=1024)
// 128x128 tile, BK=64 halves, double buffer, 2 CTAs/SM, ldmatrix fragments.
// ===========================================================================
#define BK 64
#define NC (Dm / BK)                   // 16
#define OP_BYTES (128 * LDH * 2)       // 18432 per operand per stage
#define STAGE_BYTES (2 * OP_BYTES)     // 36864 (A then W)
#define GSMEM (2 * STAGE_BYTES)        // 73728

__device__ __forceinline__ void load_chunk(uint32_t sbase, int stage,
                                           const __half* A, const __half* W,
                                           int row0, int col0, int kb, int tid) {
    uint32_t a_st = sbase + stage * STAGE_BYTES;
    uint32_t w_st = a_st + OP_BYTES;
    #pragma unroll
    for (int p = 0; p < 4; p++) {
        int idx = tid + p * 256;          // 0..1023
        int r  = idx >> 3;                // 0..127
        int cq = idx & 7;                 // 16B unit within 128B row
        uint32_t d = (uint32_t)(r * (LDH * 2) + cq * 16);
        cp16(a_st + d, A + (size_t)(row0 + r) * Dm + kb + cq * 8);
        cp16(w_st + d, W + (size_t)(col0 + r) * Dm + kb + cq * 8);
    }
    cp_commit();
}

__global__ __launch_bounds__(256, 2) void gemm_tc(float* __restrict__ Cp,
                                                  int asel, int wsel, int csel)
{
    extern __shared__ char smem[];
    uint32_t sbase = smem_u32(smem);
    const int az = (asel < 0) ? (int)blockIdx.z : asel;
    const int wz = (asel < 0) ? (int)blockIdx.z : wsel;
    const int cz = (asel < 0) ? (int)blockIdx.z + 1 : csel;

    const __half* A = (az == 0) ? g_qc : (az == 1) ? g_kc
                     : (az == 2) ? g_vc : g_ao;
    const __half* W = g_wc + (size_t)wz * WEL;
    __half* Cu = (cz == 1) ? g_xq : (cz == 2) ? g_xk : g_xv;

    const int tid = threadIdx.x;
    const int wid = tid >> 5;
    const int lid = tid & 31;
    const int g   = lid >> 2;
    const int tg  = lid & 3;
    const int wr  = wid >> 2;              // warp row 0..1 (64 rows)
    const int wc  = wid & 3;               // warp col 0..3 (32 cols)
    const int row0 = blockIdx.y * 128;
    const int col0 = blockIdx.x * 128;

    // ldmatrix lane offset (halves)
    const int sub = lid >> 3, lr = lid & 7;
    const uint32_t lane_off = (uint32_t)(((sub & 1) * 8 + lr) * LDH + (sub >> 1) * 8) * 2;

    float acc[4][4][4];
    #pragma unroll
    for (int mt = 0; mt < 4; mt++)
        #pragma unroll
        for (int nt = 0; nt < 4; nt++)
            #pragma unroll
            for (int q = 0; q < 4; q++) acc[mt][nt][q] = 0.f;

    load_chunk(sbase, 0, A, W, row0, col0, 0, tid);

    for (int c = 0; c < NC; c++) {
        if (c + 1 < NC) {
            load_chunk(sbase, (c + 1) & 1, A, W, row0, col0, (c + 1) * BK, tid);
            cp_wait<1>();
        } else {
            cp_wait<0>();
        }
        __syncthreads();

        uint32_t a_base = sbase + (c & 1) * STAGE_BYTES + lane_off;
        uint32_t w_base = a_base + OP_BYTES;

        #pragma unroll
        for (int ks = 0; ks < 4; ks++) {
            const uint32_t k0b = (uint32_t)(ks * 16) * 2;
            uint32_t af[4][4];
            #pragma unroll
            for (int mt = 0; mt < 4; mt++)
                ldsm4(af[mt], a_base + (uint32_t)((wr * 64 + mt * 16) * LDH) * 2 + k0b);
            #pragma unroll
            for (int ntp = 0; ntp < 2; ntp++) {
                uint32_t bq[4];
                ldsm4(bq, w_base + (uint32_t)((wc * 32 + ntp * 16) * LDH) * 2 + k0b);
                #pragma unroll
                for (int mt = 0; mt < 4; mt++) {
                    mma_f16(acc[mt][2 * ntp],     af[mt], bq[0], bq[2]);
                    mma_f16(acc[mt][2 * ntp + 1], af[mt], bq[1], bq[3]);
                }
            }
        }
        __syncthreads();
    }

    #pragma unroll
    for (int mt = 0; mt < 4; mt++) {
        int row = row0 + wr * 64 + mt * 16 + g;
        #pragma unroll
        for (int nt = 0; nt < 4; nt++) {
            int col = col0 + wc * 32 + nt * 8 + 2 * tg;
            if (cz == 0) {
                *reinterpret_cast<float2*>(&Cp[(size_t)row * Dm + col]) =
                    make_float2(acc[mt][nt][0], acc[mt][nt][1]);
                *reinterpret_cast<float2*>(&Cp[(size_t)(row + 8) * Dm + col]) =
                    make_float2(acc[mt][nt][2], acc[mt][nt][3]);
            } else {
                *reinterpret_cast<uint32_t*>(&Cu[(size_t)row * Dm + col]) =
                    pack_h2(acc[mt][nt][0], acc[mt][nt][1]);
                *reinterpret_cast<uint32_t*>(&Cu[(size_t)(row + 8) * Dm + col]) =
                    pack_h2(acc[mt][nt][2], acc[mt][nt][3]);
            }
        }
    }
}

// ===========================================================================
// Flash attention (causal), fp16 mma, ldmatrix, double-buffered KV, 2 CTAs/SM.
// BQ=128 (8 warps x 16 rows), BKV=64, HD=64, 256 threads.
// ===========================================================================
#define QS_OFF 0                               // [128][LDH] 18432 B
#define PS_OFF (128 * LDH * 2)                 // [128][LDH] 18432 B
#define KS_OFF (PS_OFF + 128 * LDH * 2)        // 2 x [64][LDH] 9216 B each
#define KV_STAGE (64 * LDH * 2)                // 9216
#define VS_OFF (KS_OFF + 2 * KV_STAGE)
#define AT_SMEM (VS_OFF + 2 * KV_STAGE)        // 73728 B

__device__ __forceinline__ void load_kv(uint32_t sbase, int stage,
                                        const __half* Kp, const __half* Vp,
                                        int jt, int tid) {
    uint32_t k_st = sbase + KS_OFF + stage * KV_STAGE;
    uint32_t v_st = sbase + VS_OFF + stage * KV_STAGE;
    #pragma unroll
    for (int p = 0; p < 2; p++) {
        int idx = tid + p * 256;       // 0..511
        int r   = idx >> 3;            // 0..63
        int cq  = idx & 7;
        size_t goff = (size_t)(jt * 64 + r) * Dm + cq * 8;
        uint32_t d = (uint32_t)(r * (LDH * 2) + cq * 16);
        cp16(k_st + d, Kp + goff);
        cp16(v_st + d, Vp + goff);
    }
    cp_commit();
}

__global__ __launch_bounds__(256, 2) void flash_attn_tc()
{
    extern __shared__ char smem[];
    uint32_t sbase = smem_u32(smem);
    __half* Ph = (__half*)(smem + PS_OFF);

    const int qt = (gridDim.x - 1) - blockIdx.x;   // heavy tiles first
    const int bh = blockIdx.y;
    const int b  = bh >> 4;
    const int h  = bh & 15;
    const int q0 = qt * 128;

    const size_t base = (size_t)b * Sq * Dm + (size_t)h * HD;
    const __half* Qp = g_xq + base;
    const __half* Kp = g_xk + base;
    const __half* Vp = g_xv + base;
    __half*       Op = g_ao + base;

    const int tid = threadIdx.x;
    const int wid = tid >> 5;
    const int lid = tid & 31;
    const int g   = lid >> 2;
    const int tg  = lid & 3;
    const int wrow = wid * 16;
    const int ntl = 2 * qt + 2;

    const int sub = lid >> 3, lr = lid & 7;
    const uint32_t lane_off = (uint32_t)(((sub & 1) * 8 + lr) * LDH + (sub >> 1) * 8) * 2;

    // ---- Prologue: stage Q (group 0), KV tile 0 (group 1) -----------------
    {
        uint32_t q_st = sbase + QS_OFF;
        #pragma unroll
        for (int p = 0; p < 4; p++) {
            int idx = tid + p * 256;       // 0..1023
            int r   = idx >> 3;            // 0..127
            int cq  = idx & 7;
            cp16(q_st + (uint32_t)(r * (LDH * 2) + cq * 16),
                 Qp + (size_t)(q0 + r) * Dm + cq * 8);
        }
        cp_commit();
    }
    load_kv(sbase, 0, Kp, Vp, 0, tid);
    cp_wait<1>();                // Q resident (groups complete in order)
    __syncthreads();

    // Cache Q fragments (16 regs)
    uint32_t qf[4][4];
    {
        uint32_t qb = sbase + QS_OFF + (uint32_t)(wrow * LDH) * 2 + lane_off;
        #pragma unroll
        for (int kt = 0; kt < 4; kt++)
            ldsm4(qf[kt], qb + (uint32_t)(kt * 16) * 2);
    }

    float m0 = -1e30f, m1 = -1e30f, l0 = 0.f, l1 = 0.f;
    float o[8][4];
    #pragma unroll
    for (int nt = 0; nt < 8; nt++)
        #pragma unroll
        for (int q = 0; q < 4; q++) o[nt][q] = 0.f;

    const int row_g  = q0 + wrow + g;
    const int row_g8 = row_g + 8;

    for (int jt = 0; jt < ntl; jt++) {
        const int s = jt & 1;
        if (jt + 1 < ntl) {
            load_kv(sbase, s ^ 1, Kp, Vp, jt + 1, tid);
            cp_wait<1>();          // tile jt resident
        } else {
            cp_wait<0>();
        }
        __syncthreads();

        if (jt * 64 <= q0 + wrow + 15) {
            uint32_t k_base = sbase + KS_OFF + s * KV_STAGE + lane_off;
            uint32_t v_base = sbase + VS_OFF + s * KV_STAGE + lane_off;

            // ---- S = Q K^T ----
            float sacc[8][4];
            #pragma unroll
            for (int nt = 0; nt < 8; nt++)
                #pragma unroll
                for (int q = 0; q < 4; q++) sacc[nt][q] = 0.f;

            #pragma unroll
            for (int kt = 0; kt < 4; kt++) {
                const uint32_t k0b = (uint32_t)(kt * 16) * 2;
                #pragma unroll
                for (int ntp = 0; ntp < 4; ntp++) {
                    uint32_t bq[4];
                    ldsm4(bq, k_base + (uint32_t)((ntp * 16) * LDH) * 2 + k0b);
                    mma_f16(sacc[2 * ntp],     qf[kt], bq[0], bq[2]);
                    mma_f16(sacc[2 * ntp + 1], qf[kt], bq[1], bq[3]);
                }
            }

            // ---- Causal mask (diagonal tiles only) ----
            if (jt >= 2 * qt) {
                #pragma unroll
                for (int nt = 0; nt < 8; nt++) {
                    int cb = jt * 64 + nt * 8 + 2 * tg;
                    if (cb     > row_g ) sacc[nt][0] = -1e30f;
                    if (cb + 1 > row_g ) sacc[nt][1] = -1e30f;
                    if (cb     > row_g8) sacc[nt][2] = -1e30f;
                    if (cb + 1 > row_g8) sacc[nt][3] = -1e30f;
                }
            }

            // ---- Online softmax ----
            float mn0 = m0, mn1 = m1;
            #pragma unroll
            for (int nt = 0; nt < 8; nt++) {
                mn0 = fmaxf(mn0, fmaxf(sacc[nt][0], sacc[nt][1]));
                mn1 = fmaxf(mn1, fmaxf(sacc[nt][2], sacc[nt][3]));
            }
            mn0 = fmaxf(mn0, __shfl_xor_sync(0xffffffffu, mn0, 1));
            mn0 = fmaxf(mn0, __shfl_xor_sync(0xffffffffu, mn0, 2));
            mn1 = fmaxf(mn1, __shfl_xor_sync(0xffffffffu, mn1, 1));
            mn1 = fmaxf(mn1, __shfl_xor_sync(0xffffffffu, mn1, 2));

            float sc0 = __expf(m0 - mn0);
            float sc1 = __expf(m1 - mn1);
            m0 = mn0; m1 = mn1;

            float ls0 = 0.f, ls1 = 0.f;
            #pragma unroll
            for (int nt = 0; nt < 8; nt++) {
                float p0 = __expf(sacc[nt][0] - mn0);
                float p1 = __expf(sacc[nt][1] - mn0);
                float p2 = __expf(sacc[nt][2] - mn1);
                float p3 = __expf(sacc[nt][3] - mn1);
                ls0 += p0 + p1;
                ls1 += p2 + p3;
                int col = nt * 8 + 2 * tg;
                *reinterpret_cast<uint32_t*>(&Ph[(wrow + g) * LDH + col]) =
                    pack_h2(p0, p1);
                *reinterpret_cast<uint32_t*>(&Ph[(wrow + g + 8) * LDH + col]) =
                    pack_h2(p2, p3);
            }
            ls0 += __shfl_xor_sync(0xffffffffu, ls0, 1);
            ls0 += __shfl_xor_sync(0xffffffffu, ls0, 2);
            ls1 += __shfl_xor_sync(0xffffffffu, ls1, 1);
            ls1 += __shfl_xor_sync(0xffffffffu, ls1, 2);
            l0 = l0 * sc0 + ls0;
            l1 = l1 * sc1 + ls1;

            #pragma unroll
            for (int nt = 0; nt < 8; nt++) {
                o[nt][0] *= sc0; o[nt][1] *= sc0;
                o[nt][2] *= sc1; o[nt][3] *= sc1;
            }
            __syncwarp();

            // ---- O += P V  (A = P via ldmatrix, B = V via ldmatrix.trans) --
            uint32_t p_base = sbase + PS_OFF + (uint32_t)(wrow * LDH) * 2 + lane_off;
            #pragma unroll
            for (int kt = 0; kt < 4; kt++) {
                const int k0 = kt * 16;
                uint32_t ap[4];
                ldsm4(ap, p_base + (uint32_t)k0 * 2);
                #pragma unroll
                for (int ntp = 0; ntp < 4; ntp++) {
                    uint32_t bq[4];
                    ldsm4t(bq, v_base + (uint32_t)(k0 * LDH + ntp * 16) * 2);
                    mma_f16(o[2 * ntp],     ap, bq[0], bq[1]);
                    mma_f16(o[2 * ntp + 1], ap, bq[2], bq[3]);
                }
            }
        }
        __syncthreads();   // stage s free for the prefetch issued next iter
    }

    // ---- Epilogue: normalize, write fp16 O ----
    float il0 = 1.f / l0, il1 = 1.f / l1;
    #pragma unroll
    for (int nt = 0; nt < 8; nt++) {
        int col = nt * 8 + 2 * tg;
        *reinterpret_cast<uint32_t*>(&Op[(size_t)(row_g) * Dm + col]) =
            pack_h2(o[nt][0] * il0, o[nt][1] * il0);
        *reinterpret_cast<uint32_t*>(&Op[(size_t)(row_g8) * Dm + col]) =
            pack_h2(o[nt][2] * il1, o[nt][3] * il1);
    }
}

// ---------------------------------------------------------------------------
// Launch
// ---------------------------------------------------------------------------
extern "C" void kernel_launch(void* const* d_in, const int* in_sizes, int n_in,
                              void* d_out, int out_size)
{
    const float* q  = (const float*)d_in[0];
    const float* k  = (const float*)d_in[1];
    const float* v  = (const float*)d_in[2];
    const float* wq = (const float*)d_in[3];
    const float* wk = (const float*)d_in[4];
    const float* wv = (const float*)d_in[5];
    const float* wo = (const float*)d_in[6];
    float* out = (float*)d_out;

    cudaFuncSetAttribute(gemm_tc, cudaFuncAttributeMaxDynamicSharedMemorySize,
                         GSMEM);
    cudaFuncSetAttribute(flash_attn_tc,
                         cudaFuncAttributeMaxDynamicSharedMemorySize, AT_SMEM);

    conv_all<<<CONV_BLOCKS, 256>>>(q, k, v, wq, wk, wv, wo);

    dim3 gqkv(Dm / 128, MTOT / 128, 3);    // fused Q/K/V projections
    gemm_tc<<<gqkv, 256, GSMEM>>>(nullptr, -1, 0, 0);

    dim3 agrid(Sq / 128, Bsz * Hh, 1);     // (16, 64)
    flash_attn_tc<<<agrid, 256, AT_SMEM>>>();

    dim3 ggrid(Dm / 128, MTOT / 128, 1);   // O projection
    gemm_tc<<<ggrid, 256, GSMEM>>>(out, 3, 3, 0);
}